// round 6
// baseline (speedup 1.0000x reference)
#include <cuda_runtime.h>
#include <cuda_bf16.h>
#include <math.h>
#include <stdint.h>

#define Nn 131072
#define Bb 4096
#define Ee 512
#define Hh 8
#define Dd 64
#define EE (Ee*Ee)

// ---------------- scratch (device globals; no allocation allowed) ----------------
__device__ __align__(16) float g_Acat[4*EE];
__device__ __align__(16) float g_Bcat[4*EE];
__device__ __align__(16) float g_Weff[4*EE];          // [Wq_eff; Wk_eff; Wv_eff; Wo_eff]
__device__ __align__(16) float g_beff[3*Ee];          // [bq_eff; bv_eff; bo_eff]
__device__ __align__(16) float g_qq[Bb*Ee];
__device__ __align__(16) float g_qhat[(size_t)Bb*Hh*Ee];
__device__ int   g_segstart[Bb+1];
__device__ __align__(16) float g_xw[(size_t)Bb*Hh*Ee];
__device__ __align__(16) float g_pooled[Bb*Ee];
__device__ __align__(16) float g_outbuf[Bb*Ee];

// ================= mma.sync helpers (compute_103 baseline features) =============
__device__ __forceinline__ uint32_t smem_u32(const void* p) {
    uint32_t a;
    asm("{ .reg .u64 t; cvta.to.shared.u64 t, %1; cvt.u32.u64 %0, t; }" : "=r"(a) : "l"(p));
    return a;
}

__device__ __forceinline__ void ldsm4(uint32_t* r, uint32_t addr) {
    asm volatile("ldmatrix.sync.aligned.m8n8.x4.shared.b16 {%0,%1,%2,%3}, [%4];"
        : "=r"(r[0]), "=r"(r[1]), "=r"(r[2]), "=r"(r[3]) : "r"(addr));
}
__device__ __forceinline__ void mma16816(float* c, const uint32_t* a, const uint32_t* b) {
    asm volatile("mma.sync.aligned.m16n8k16.row.col.f32.bf16.bf16.f32 "
        "{%0,%1,%2,%3}, {%4,%5,%6,%7}, {%8,%9}, {%0,%1,%2,%3};"
        : "+f"(c[0]), "+f"(c[1]), "+f"(c[2]), "+f"(c[3])
        : "r"(a[0]), "r"(a[1]), "r"(a[2]), "r"(a[3]), "r"(b[0]), "r"(b[1]));
}

// ---------- fp32 -> bf16 hi/lo split ----------
__device__ __forceinline__ void split4(float4 v, uint2& hi, uint2& lo) {
    __nv_bfloat162 h0 = __floats2bfloat162_rn(v.x, v.y);
    __nv_bfloat162 h1 = __floats2bfloat162_rn(v.z, v.w);
    float2 f0 = __bfloat1622float2(h0);
    float2 f1 = __bfloat1622float2(h1);
    __nv_bfloat162 l0 = __floats2bfloat162_rn(v.x - f0.x, v.y - f0.y);
    __nv_bfloat162 l1 = __floats2bfloat162_rn(v.z - f1.x, v.w - f1.y);
    hi.x = *(uint32_t*)&h0; hi.y = *(uint32_t*)&h1;
    lo.x = *(uint32_t*)&l0; lo.y = *(uint32_t*)&l1;
}

// ================= HMMA GEMM, double-buffered + register-prefetch pipeline =======
// C[M,N] = alpha * A @ op(B) (+ bias), z-batched. BM=128, BN=64, BK=32.
// fp32 emulated as bf16 hi/lo: hi*hi + hi*lo + lo*hi.  M%128==0, N%64==0, K%32==0.
// SMEM row stride 80B: 8-row ldmatrix segments land on 8 distinct 16B banks.
// B is ALWAYS stored as [n rows][k cols] in SMEM (the !TRANSB path transposes
// during the store), so the MMA read path is a single non-trans ldmatrix.
#define ROWB 80
#define ST_ALO 10240
#define ST_BHI 20480
#define ST_BLO 25600
#define ST_SZ  30720
#define SM_TOTAL (2*ST_SZ)

template<bool TRANSB, bool HASBIAS>
__global__ void __launch_bounds__(256, 2)
tcgemm(const float* __restrict__ A, const float* __restrict__ B,
       float* __restrict__ C, const float* __restrict__ bias,
       int K, int lda, int ldb, int ldc,
       long zA, long zB, long zC, int zBias, float alpha)
{
    extern __shared__ __align__(16) char sm[];
    uint32_t sb = smem_u32(sm);

    int z = blockIdx.z;
    A += (long)z * zA;
    B += (long)z * zB;
    C += (long)z * zC;
    int bm = blockIdx.y * 128;
    int bn = blockIdx.x * 64;
    int tid = threadIdx.x;
    int wid = tid >> 5;
    int lane = tid & 31;
    int wm = wid & 3;
    int wn = wid >> 2;

    float acc[2][4][4];
#pragma unroll
    for (int i = 0; i < 2; i++)
#pragma unroll
        for (int f = 0; f < 4; f++)
#pragma unroll
            for (int r = 0; r < 4; r++) acc[i][f][r] = 0.f;

    // ldmatrix per-thread address components (non-trans, used for A and B)
    int am = ((lane >> 3) & 1) * 8 + (lane & 7);
    int ak = (lane >> 4) * 8;
    int bnr = ((lane >> 4) & 1) * 8 + (lane & 7);
    int bkc = ((lane >> 3) & 1) * 8;

    // per-thread load/store index precompute
    int arow = tid >> 3, ac4 = tid & 7;          // A: 4 x (row += 32)
    int brow = tid >> 3, bc4 = tid & 7;          // B TRANSB: 2 x (row += 32)
    int bkrow = tid >> 4, bn4 = tid & 15;        // B !TRANSB: 2 x (krow += 16)

    float4 pa[4];
    float4 pb[2];

#define LOADA(k0) do { \
    _Pragma("unroll") \
    for (int i = 0; i < 4; i++) \
        pa[i] = *(const float4*)&A[(long)(bm + arow + 32 * i) * lda + (k0) + ac4 * 4]; \
} while (0)

#define LOADB(k0) do { \
    if (TRANSB) { \
        _Pragma("unroll") \
        for (int i = 0; i < 2; i++) \
            pb[i] = *(const float4*)&B[(long)(bn + brow + 32 * i) * ldb + (k0) + bc4 * 4]; \
    } else { \
        _Pragma("unroll") \
        for (int i = 0; i < 2; i++) \
            pb[i] = *(const float4*)&B[(long)((k0) + bkrow + 16 * i) * ldb + bn + bn4 * 4]; \
    } \
} while (0)

#define STORESTAGE(base) do { \
    _Pragma("unroll") \
    for (int i = 0; i < 4; i++) { \
        uint2 hi, lo; \
        split4(pa[i], hi, lo); \
        uint32_t off = (uint32_t)(arow + 32 * i) * ROWB + ac4 * 8; \
        *(uint2*)((base) + off) = hi; \
        *(uint2*)((base) + ST_ALO + off) = lo; \
    } \
    if (TRANSB) { \
        _Pragma("unroll") \
        for (int i = 0; i < 2; i++) { \
            uint2 hi, lo; \
            split4(pb[i], hi, lo); \
            uint32_t off = (uint32_t)(brow + 32 * i) * ROWB + bc4 * 8; \
            *(uint2*)((base) + ST_BHI + off) = hi; \
            *(uint2*)((base) + ST_BLO + off) = lo; \
        } \
    } else { \
        _Pragma("unroll") \
        for (int i = 0; i < 2; i++) { \
            const float* vv = &pb[i].x; \
            _Pragma("unroll") \
            for (int j = 0; j < 4; j++) { \
                float x = vv[j]; \
                __nv_bfloat16 h = __float2bfloat16(x); \
                __nv_bfloat16 l = __float2bfloat16(x - __bfloat162float(h)); \
                uint32_t off = (uint32_t)(bn4 * 4 + j) * ROWB + (bkrow + 16 * i) * 2; \
                *(__nv_bfloat16*)((base) + ST_BHI + off) = h; \
                *(__nv_bfloat16*)((base) + ST_BLO + off) = l; \
            } \
        } \
    } \
} while (0)

    const int nch = K / 32;
    LOADA(0);
    LOADB(0);
    STORESTAGE(sm);
    __syncthreads();

    for (int ch = 0; ch < nch; ch++) {
        uint32_t cur = (ch & 1) * ST_SZ;
        bool more = (ch + 1 < nch);
        if (more) {
            int k0 = (ch + 1) * 32;
            LOADA(k0);
            LOADB(k0);
        }

#pragma unroll
        for (int ks = 0; ks < 2; ks++) {
            int kk = ks * 16;
            uint32_t bh[4][2], bl[4][2];
#pragma unroll
            for (int g = 0; g < 2; g++) {
                uint32_t r[4];
                // B SMEM is [n][k] for BOTH layouts -> single non-trans read path
                uint32_t off = cur + ST_BHI + (uint32_t)(wn * 32 + g * 16 + bnr) * ROWB + (kk + bkc) * 2;
                ldsm4(r, sb + off);
                bh[g*2][0]=r[0]; bh[g*2][1]=r[1]; bh[g*2+1][0]=r[2]; bh[g*2+1][1]=r[3];
                ldsm4(r, sb + off + (ST_BLO - ST_BHI));
                bl[g*2][0]=r[0]; bl[g*2][1]=r[1]; bl[g*2+1][0]=r[2]; bl[g*2+1][1]=r[3];
            }
            uint32_t ah[2][4], al[2][4];
#pragma unroll
            for (int i = 0; i < 2; i++) {
                uint32_t off = cur + (uint32_t)(wm * 32 + i * 16 + am) * ROWB + (kk + ak) * 2;
                ldsm4(ah[i], sb + off);
                ldsm4(al[i], sb + off + ST_ALO);
            }
#pragma unroll
            for (int i = 0; i < 2; i++)
#pragma unroll
                for (int f = 0; f < 4; f++) {
                    mma16816(acc[i][f], ah[i], bh[f]);
                    mma16816(acc[i][f], ah[i], bl[f]);
                    mma16816(acc[i][f], al[i], bh[f]);
                }
        }

        if (more) {
            STORESTAGE(sm + ((ch + 1) & 1) * ST_SZ);
        }
        __syncthreads();
    }

#pragma unroll
    for (int i = 0; i < 2; i++) {
#pragma unroll
        for (int f = 0; f < 4; f++) {
            int row = bm + wm * 32 + i * 16 + (lane >> 2);
            int col = bn + wn * 32 + f * 8 + (lane & 3) * 2;
            float2 bb = make_float2(0.f, 0.f);
            if (HASBIAS) bb = *(const float2*)&bias[(long)z * zBias + col];
            float2 o0, o1;
            o0.x = alpha * acc[i][f][0] + bb.x;
            o0.y = alpha * acc[i][f][1] + bb.y;
            o1.x = alpha * acc[i][f][2] + bb.x;
            o1.y = alpha * acc[i][f][3] + bb.y;
            *(float2*)&C[(long)row * ldc + col] = o0;
            *(float2*)&C[(long)(row + 8) * ldc + col] = o1;
        }
    }
#undef LOADA
#undef LOADB
#undef STORESTAGE
}

// ---------------- bias folding: bq_eff, bv_eff, bo_eff -----------------
__global__ void bias_fold(const float* __restrict__ ipw, const float* __restrict__ ipb,
                          const float* __restrict__ bq,  const float* __restrict__ bv,
                          const float* __restrict__ out_w, const float* __restrict__ mob,
                          const float* __restrict__ out_b)
{
    int gw = (blockIdx.x * blockDim.x + threadIdx.x) >> 5;
    int lane = threadIdx.x & 31;
    if (gw >= 3 * Ee) return;
    int which = gw / Ee, i = gw % Ee;
    const float* rowp;
    const float* vec;
    float add;
    if (which == 0)      { rowp = ipw + (long)i * Ee;            vec = bq;  add = ipb[i]; }
    else if (which == 1) { rowp = ipw + (long)(2 * Ee + i) * Ee; vec = bv;  add = ipb[2 * Ee + i]; }
    else                 { rowp = out_w + (long)i * Ee;          vec = mob; add = out_b[i]; }
    float s = 0.f;
    for (int k = lane; k < Ee; k += 32) s += rowp[k] * vec[k];
#pragma unroll
    for (int o = 16; o; o >>= 1) s += __shfl_xor_sync(0xffffffffu, s, o);
    if (lane == 0) g_beff[gw] = s + add;
}

// ---------------- segment starts (batch sorted, all B present) -----------------
__global__ void segstart_kernel(const int* __restrict__ batch)
{
    int n = blockIdx.x * 256 + threadIdx.x;
    if (n < Nn) {
        int b = batch[n];
        if (n == 0 || batch[n - 1] != b) g_segstart[b] = n;
    }
    if (n == 0) g_segstart[Bb] = Nn;
}

// ================= fused segment attention =================
__global__ void __launch_bounds__(256) fused_attn_kernel(const float* __restrict__ X)
{
    __shared__ float qsh[4096];        // qhat[b]  [8][512]
    __shared__ float lgsh[32][9];      // chunk logits (padded)
    __shared__ float psh[32][8];       // chunk p values
    __shared__ float st_m[8], st_Z[8], st_f[8];

    int b = blockIdx.x;
    int t = threadIdx.x;
    int w = t >> 5, lane = t & 31;
    int s0 = g_segstart[b], e0 = g_segstart[b + 1];

    {
        const float4* src = (const float4*)(g_qhat + (size_t)b * (Hh * Ee));
        float4* dst = (float4*)qsh;
#pragma unroll
        for (int i = 0; i < 4; i++) dst[t + 256 * i] = src[t + 256 * i];
    }
    if (t < 8) { st_m[t] = -1e30f; st_Z[t] = 0.f; }
    __syncthreads();

    float acc[8][2];
#pragma unroll
    for (int h = 0; h < 8; h++) { acc[h][0] = 0.f; acc[h][1] = 0.f; }

    for (int base = s0; base < e0; base += 32) {
        int cnt = min(32, e0 - base);

        // ---- phase A: logits, 4 nodes per warp ----
        {
            int nb = base + 4 * w;
            float4 xv[4][4];
#pragma unroll
            for (int j = 0; j < 4; j++) {
                int n = nb + j;
                if (n < e0) {
                    const float4* xr = (const float4*)(X + (size_t)n * Ee);
#pragma unroll
                    for (int i = 0; i < 4; i++) xv[j][i] = xr[lane + 32 * i];
                } else {
#pragma unroll
                    for (int i = 0; i < 4; i++) xv[j][i] = make_float4(0.f, 0.f, 0.f, 0.f);
                }
            }
#pragma unroll
            for (int h = 0; h < 8; h++) {
                const float4* q = (const float4*)qsh + h * 128;
                float4 q0 = q[lane], q1 = q[lane + 32], q2 = q[lane + 64], q3 = q[lane + 96];
                float s[4];
#pragma unroll
                for (int j = 0; j < 4; j++) {
                    float v;
                    v  = xv[j][0].x * q0.x + xv[j][0].y * q0.y + xv[j][0].z * q0.z + xv[j][0].w * q0.w;
                    v += xv[j][1].x * q1.x + xv[j][1].y * q1.y + xv[j][1].z * q1.z + xv[j][1].w * q1.w;
                    v += xv[j][2].x * q2.x + xv[j][2].y * q2.y + xv[j][2].z * q2.z + xv[j][2].w * q2.w;
                    v += xv[j][3].x * q3.x + xv[j][3].y * q3.y + xv[j][3].z * q3.z + xv[j][3].w * q3.w;
                    s[j] = v;
                }
#pragma unroll
                for (int o = 16; o; o >>= 1) {
#pragma unroll
                    for (int j = 0; j < 4; j++) s[j] += __shfl_xor_sync(0xffffffffu, s[j], o);
                }
                if (lane == 0) {
#pragma unroll
                    for (int j = 0; j < 4; j++)
                        lgsh[4 * w + j][h] = (nb + j < e0) ? s[j] : -1e30f;
                }
            }
        }
        __syncthreads();

        // ---- stats: warp w handles head w ----
        if (w < 8) {
            float v = (lane < cnt) ? lgsh[lane][w] : -1e30f;
            float mx = v;
#pragma unroll
            for (int o = 16; o; o >>= 1) mx = fmaxf(mx, __shfl_xor_sync(0xffffffffu, mx, o));
            float mo = st_m[w];
            float mn = fmaxf(mo, mx);
            float p = (lane < cnt) ? __expf(v - mn) : 0.f;
            psh[lane][w] = p;
            float ssum = p;
#pragma unroll
            for (int o = 16; o; o >>= 1) ssum += __shfl_xor_sync(0xffffffffu, ssum, o);
            if (lane == 0) {
                float f = __expf(mo - mn);
                st_f[w] = f;
                st_m[w] = mn;
                st_Z[w] = st_Z[w] * f + ssum;
            }
        }
        __syncthreads();

        // ---- rescale + phase C ----
#pragma unroll
        for (int h = 0; h < 8; h++) {
            float f = st_f[h];
            acc[h][0] *= f;
            acc[h][1] *= f;
        }
        int i = 0;
        for (; i + 4 <= cnt; i += 4) {
            float2 x0 = *(const float2*)&X[(size_t)(base + i + 0) * Ee + 2 * t];
            float2 x1 = *(const float2*)&X[(size_t)(base + i + 1) * Ee + 2 * t];
            float2 x2 = *(const float2*)&X[(size_t)(base + i + 2) * Ee + 2 * t];
            float2 x3 = *(const float2*)&X[(size_t)(base + i + 3) * Ee + 2 * t];
#pragma unroll
            for (int j = 0; j < 4; j++) {
                float2 x = (j == 0) ? x0 : (j == 1) ? x1 : (j == 2) ? x2 : x3;
                float4 p0 = *(const float4*)&psh[i + j][0];
                float4 p1 = *(const float4*)&psh[i + j][4];
                float pw[8] = {p0.x, p0.y, p0.z, p0.w, p1.x, p1.y, p1.z, p1.w};
#pragma unroll
                for (int h = 0; h < 8; h++) {
                    acc[h][0] += pw[h] * x.x;
                    acc[h][1] += pw[h] * x.y;
                }
            }
        }
        for (; i < cnt; i++) {
            float2 x = *(const float2*)&X[(size_t)(base + i) * Ee + 2 * t];
            float4 p0 = *(const float4*)&psh[i][0];
            float4 p1 = *(const float4*)&psh[i][4];
            float pw[8] = {p0.x, p0.y, p0.z, p0.w, p1.x, p1.y, p1.z, p1.w};
#pragma unroll
            for (int h = 0; h < 8; h++) {
                acc[h][0] += pw[h] * x.x;
                acc[h][1] += pw[h] * x.y;
            }
        }
        __syncthreads();
    }

    float rZ[8];
#pragma unroll
    for (int h = 0; h < 8; h++) rZ[h] = 1.f / st_Z[h];
#pragma unroll
    for (int h = 0; h < 8; h++) {
        float2 o = make_float2(acc[h][0] * rZ[h], acc[h][1] * rZ[h]);
        *(float2*)&g_xw[((size_t)b * Hh + h) * Ee + 2 * t] = o;
    }
}

// ---------------- LayerNorm over rows of outbuf -> d_out -----------------
__global__ void __launch_bounds__(256) ln_kernel(const float* __restrict__ lng,
                                                 const float* __restrict__ lnb,
                                                 float* __restrict__ out)
{
    int b = blockIdx.x;
    int t = threadIdx.x;
    float v0 = g_outbuf[(long)b * Ee + t];
    float v1 = g_outbuf[(long)b * Ee + t + 256];
    float s = v0 + v1;
    float q = v0 * v0 + v1 * v1;
#pragma unroll
    for (int o = 16; o; o >>= 1) {
        s += __shfl_xor_sync(0xffffffffu, s, o);
        q += __shfl_xor_sync(0xffffffffu, q, o);
    }
    __shared__ float ss[8], qs[8];
    __shared__ float mu_s, r_s;
    int wid = t >> 5, lane = t & 31;
    if (lane == 0) { ss[wid] = s; qs[wid] = q; }
    __syncthreads();
    if (t == 0) {
        float S = 0.f, Q = 0.f;
#pragma unroll
        for (int i = 0; i < 8; i++) { S += ss[i]; Q += qs[i]; }
        float mu = S / (float)Ee;
        float var = Q / (float)Ee - mu * mu;
        mu_s = mu;
        r_s = 1.f / sqrtf(var + 1e-5f);
    }
    __syncthreads();
    float mu = mu_s, r = r_s;
    out[(long)b * Ee + t]       = (v0 - mu) * r * lng[t]       + lnb[t];
    out[(long)b * Ee + t + 256] = (v1 - mu) * r * lng[t + 256] + lnb[t + 256];
}

// ---------------- launch -----------------
extern "C" void kernel_launch(void* const* d_in, const int* in_sizes, int n_in,
                              void* d_out, int out_size)
{
    (void)in_sizes; (void)n_in; (void)out_size;
    const float* X        = (const float*)d_in[0];   // node_features [N,E]
    const float* scaffold = (const float*)d_in[1];   // [B,E]
    const float* Wq       = (const float*)d_in[2];
    const float* bq       = (const float*)d_in[3];
    const float* Wk       = (const float*)d_in[4];
    const float* Wv       = (const float*)d_in[6];
    const float* bv       = (const float*)d_in[7];
    const float* ipw      = (const float*)d_in[8];   // in_proj_w [3E,E]
    const float* ipb      = (const float*)d_in[9];
    const float* mow      = (const float*)d_in[10];  // mha_out_w
    const float* mob      = (const float*)d_in[11];
    const float* ow       = (const float*)d_in[12];  // out_w
    const float* ob       = (const float*)d_in[13];
    const float* lng      = (const float*)d_in[14];
    const float* lnb      = (const float*)d_in[15];
    const int*   batch    = (const int*)d_in[16];

    void* p;
    cudaGetSymbolAddress(&p, g_Acat);   float* Acat   = (float*)p;
    cudaGetSymbolAddress(&p, g_Bcat);   float* Bcat   = (float*)p;
    cudaGetSymbolAddress(&p, g_Weff);   float* Weff   = (float*)p;
    cudaGetSymbolAddress(&p, g_beff);   float* beff   = (float*)p;
    cudaGetSymbolAddress(&p, g_qq);     float* qq     = (float*)p;
    cudaGetSymbolAddress(&p, g_qhat);   float* qhat   = (float*)p;
    cudaGetSymbolAddress(&p, g_xw);     float* xw     = (float*)p;
    cudaGetSymbolAddress(&p, g_pooled); float* pooled = (float*)p;
    cudaGetSymbolAddress(&p, g_outbuf); float* outbuf = (float*)p;

    cudaFuncSetAttribute(tcgemm<false, false>,
                         cudaFuncAttributeMaxDynamicSharedMemorySize, SM_TOTAL);
    cudaFuncSetAttribute(tcgemm<true, true>,
                         cudaFuncAttributeMaxDynamicSharedMemorySize, SM_TOTAL);

    // concat fold operands: Acat=[Wiq;Wik;Wiv;out_w], Bcat=[Wq;Wk;Wv;mha_out_w]
    cudaMemcpyAsync(Acat,          ipw, (size_t)3 * EE * sizeof(float), cudaMemcpyDeviceToDevice, 0);
    cudaMemcpyAsync(Acat + 3 * EE, ow,  (size_t)EE * sizeof(float),     cudaMemcpyDeviceToDevice, 0);
    cudaMemcpyAsync(Bcat,          Wq,  (size_t)EE * sizeof(float),     cudaMemcpyDeviceToDevice, 0);
    cudaMemcpyAsync(Bcat + EE,     Wk,  (size_t)EE * sizeof(float),     cudaMemcpyDeviceToDevice, 0);
    cudaMemcpyAsync(Bcat + 2 * EE, Wv,  (size_t)EE * sizeof(float),     cudaMemcpyDeviceToDevice, 0);
    cudaMemcpyAsync(Bcat + 3 * EE, mow, (size_t)EE * sizeof(float),     cudaMemcpyDeviceToDevice, 0);

    // fold: Weff[z] = Acat[z] @ Bcat[z]  (z = q,k,v,o), 512x512x512 each (NN)
    tcgemm<false, false><<<dim3(8, 4, 4), 256, SM_TOTAL>>>(Acat, Bcat, Weff, nullptr,
        512, 512, 512, 512, (long)EE, (long)EE, (long)EE, 0, 1.f);

    bias_fold<<<192, 256>>>(ipw, ipb, bq, bv, ow, mob, ob);

    // qq = scaffold @ Wq_eff^T + bq_eff   [4096,512,512] NT
    tcgemm<true, true><<<dim3(8, 32, 1), 256, SM_TOTAL>>>(scaffold, Weff, qq, beff,
        512, Ee, Ee, Ee, 0, 0, 0, 0, 1.f);

    // qhat[b,h,:] = scale * qq[b,h,:] @ Wk_eff_h    [4096,512,64] NN x 8 heads
    tcgemm<false, false><<<dim3(8, 32, 8), 256, SM_TOTAL>>>(qq, Weff + EE, qhat, nullptr,
        Dd, Ee, Ee, Hh * Ee, (long)Dd, (long)Dd * Ee, (long)Ee, 0, 0.125f);

    segstart_kernel<<<Nn / 256, 256>>>(batch);

    // fused logits + online softmax + weighted sum
    fused_attn_kernel<<<Bb, 256>>>(X);

    // pooled[b, h*D+:] = xw[b,h,:] @ Wv_eff_h^T + bv_eff   [4096,64,512] NT x 8 heads
    tcgemm<true, true><<<dim3(1, 32, 8), 256, SM_TOTAL>>>(xw, Weff + 2 * EE, pooled, beff + Ee,
        512, Hh * Ee, Ee, Ee, (long)Ee, (long)Dd * Ee, (long)Dd, Dd, 1.f);

    // out = pooled @ Wo_eff^T + bo_eff   [4096,512,512] NT
    tcgemm<true, true><<<dim3(8, 32, 1), 256, SM_TOTAL>>>(pooled, Weff + 3 * EE, outbuf, beff + 2 * Ee,
        512, Ee, Ee, Ee, 0, 0, 0, 0, 1.f);

    ln_kernel<<<Bb, 256>>>(lng, lnb, (float*)d_out);
}

// round 7
// speedup vs baseline: 1.0380x; 1.0380x over previous
#include <cuda_runtime.h>
#include <cuda_bf16.h>
#include <math.h>
#include <stdint.h>

#define Nn 131072
#define Bb 4096
#define Ee 512
#define Hh 8
#define Dd 64
#define EE (Ee*Ee)

// ---------------- scratch (device globals; no allocation allowed) ----------------
__device__ __align__(16) float g_Acat[4*EE];
__device__ __align__(16) float g_Bcat[4*EE];
__device__ __align__(16) float g_Weff[4*EE];          // [Wq_eff; Wk_eff; Wv_eff; Wo_eff]
__device__ __align__(16) float g_beff[3*Ee];          // [bq_eff; bv_eff; bo_eff]
__device__ __align__(16) float g_qq[Bb*Ee];
__device__ __align__(16) float g_qhat[(size_t)Bb*Hh*Ee];
__device__ int   g_segstart[Bb+1];
__device__ __align__(16) float g_xw[(size_t)Bb*Hh*Ee];
__device__ __align__(16) float g_pooled[Bb*Ee];
__device__ __align__(16) float g_outbuf[Bb*Ee];

// ================= mma.sync helpers (compute_103 baseline features) =============
__device__ __forceinline__ uint32_t smem_u32(const void* p) {
    uint32_t a;
    asm("{ .reg .u64 t; cvta.to.shared.u64 t, %1; cvt.u32.u64 %0, t; }" : "=r"(a) : "l"(p));
    return a;
}

__device__ __forceinline__ void ldsm4(uint32_t* r, uint32_t addr) {
    asm volatile("ldmatrix.sync.aligned.m8n8.x4.shared.b16 {%0,%1,%2,%3}, [%4];"
        : "=r"(r[0]), "=r"(r[1]), "=r"(r[2]), "=r"(r[3]) : "r"(addr));
}
__device__ __forceinline__ void ldsm4t(uint32_t* r, uint32_t addr) {
    asm volatile("ldmatrix.sync.aligned.m8n8.x4.trans.shared.b16 {%0,%1,%2,%3}, [%4];"
        : "=r"(r[0]), "=r"(r[1]), "=r"(r[2]), "=r"(r[3]) : "r"(addr));
}
__device__ __forceinline__ void mma16816(float* c, const uint32_t* a, const uint32_t* b) {
    asm volatile("mma.sync.aligned.m16n8k16.row.col.f32.bf16.bf16.f32 "
        "{%0,%1,%2,%3}, {%4,%5,%6,%7}, {%8,%9}, {%0,%1,%2,%3};"
        : "+f"(c[0]), "+f"(c[1]), "+f"(c[2]), "+f"(c[3])
        : "r"(a[0]), "r"(a[1]), "r"(a[2]), "r"(a[3]), "r"(b[0]), "r"(b[1]));
}

// ---------- fp32 -> bf16 hi/lo split ----------
__device__ __forceinline__ void split4(float4 v, uint2& hi, uint2& lo) {
    __nv_bfloat162 h0 = __floats2bfloat162_rn(v.x, v.y);
    __nv_bfloat162 h1 = __floats2bfloat162_rn(v.z, v.w);
    float2 f0 = __bfloat1622float2(h0);
    float2 f1 = __bfloat1622float2(h1);
    __nv_bfloat162 l0 = __floats2bfloat162_rn(v.x - f0.x, v.y - f0.y);
    __nv_bfloat162 l1 = __floats2bfloat162_rn(v.z - f1.x, v.w - f1.y);
    hi.x = *(uint32_t*)&h0; hi.y = *(uint32_t*)&h1;
    lo.x = *(uint32_t*)&l0; lo.y = *(uint32_t*)&l1;
}

// ================= HMMA GEMM (exact R3/R4 version, proven) =================
// C[M,N] = alpha * A @ op(B) (+ bias), z-batched. BM=128, BN=64, K chunk=64.
// fp32 emulated as bf16 hi/lo: hi*hi + hi*lo + lo*hi.  M%128==0, N%64==0, K%64==0.
#define ROWB 144
#define SM_AHI 0
#define SM_ALO 18432
#define SM_BHI 36864
#define SM_BLO 46080
#define SM_TOTAL 55296

template<bool TRANSB, bool HASBIAS>
__global__ void __launch_bounds__(256, 2)
tcgemm(const float* __restrict__ A, const float* __restrict__ B,
       float* __restrict__ C, const float* __restrict__ bias,
       int K, int lda, int ldb, int ldc,
       long zA, long zB, long zC, int zBias, float alpha)
{
    extern __shared__ __align__(16) char sm[];
    uint32_t sb = smem_u32(sm);

    int z = blockIdx.z;
    A += (long)z * zA;
    B += (long)z * zB;
    C += (long)z * zC;
    int bm = blockIdx.y * 128;
    int bn = blockIdx.x * 64;
    int tid = threadIdx.x;
    int wid = tid >> 5;
    int lane = tid & 31;
    int wm = wid & 3;
    int wn = wid >> 2;

    float acc[2][4][4];
#pragma unroll
    for (int i = 0; i < 2; i++)
#pragma unroll
        for (int f = 0; f < 4; f++)
#pragma unroll
            for (int r = 0; r < 4; r++) acc[i][f][r] = 0.f;

    int am = ((lane >> 3) & 1) * 8 + (lane & 7);
    int ak = (lane >> 4) * 8;
    int bnr = ((lane >> 4) & 1) * 8 + (lane & 7);
    int bkc = ((lane >> 3) & 1) * 8;
    int bkr = ((lane >> 3) & 1) * 8 + (lane & 7);
    int bnc = (lane >> 4) * 8;

    const int nch = K / 64;
    for (int ch = 0; ch < nch; ch++) {
        int k0 = ch * 64;

#pragma unroll
        for (int i = 0; i < 8; i++) {
            int p = tid + i * 256;
            int row = p >> 4;
            int c4 = p & 15;
            float4 v = *(const float4*)&A[(long)(bm + row) * lda + k0 + c4 * 4];
            uint2 hi, lo;
            split4(v, hi, lo);
            uint32_t off = row * ROWB + c4 * 8;
            *(uint2*)(sm + SM_AHI + off) = hi;
            *(uint2*)(sm + SM_ALO + off) = lo;
        }
#pragma unroll
        for (int i = 0; i < 4; i++) {
            int p = tid + i * 256;
            int row = p >> 4;
            int c4 = p & 15;
            const float* src = TRANSB ? &B[(long)(bn + row) * ldb + k0 + c4 * 4]
                                      : &B[(long)(k0 + row) * ldb + bn + c4 * 4];
            float4 v = *(const float4*)src;
            uint2 hi, lo;
            split4(v, hi, lo);
            uint32_t off = row * ROWB + c4 * 8;
            *(uint2*)(sm + SM_BHI + off) = hi;
            *(uint2*)(sm + SM_BLO + off) = lo;
        }
        __syncthreads();

#pragma unroll
        for (int ks = 0; ks < 4; ks++) {
            int kk = ks * 16;
            uint32_t bh[4][2], bl[4][2];
#pragma unroll
            for (int g = 0; g < 2; g++) {
                uint32_t r[4];
                if (TRANSB) {
                    uint32_t off = (uint32_t)(wn * 32 + g * 16 + bnr) * ROWB + (kk + bkc) * 2;
                    ldsm4(r, sb + SM_BHI + off);
                    bh[g*2][0]=r[0]; bh[g*2][1]=r[1]; bh[g*2+1][0]=r[2]; bh[g*2+1][1]=r[3];
                    ldsm4(r, sb + SM_BLO + off);
                    bl[g*2][0]=r[0]; bl[g*2][1]=r[1]; bl[g*2+1][0]=r[2]; bl[g*2+1][1]=r[3];
                } else {
                    uint32_t off = (uint32_t)(kk + bkr) * ROWB + (wn * 32 + g * 16 + bnc) * 2;
                    ldsm4t(r, sb + SM_BHI + off);
                    bh[g*2][0]=r[0]; bh[g*2][1]=r[1]; bh[g*2+1][0]=r[2]; bh[g*2+1][1]=r[3];
                    ldsm4t(r, sb + SM_BLO + off);
                    bl[g*2][0]=r[0]; bl[g*2][1]=r[1]; bl[g*2+1][0]=r[2]; bl[g*2+1][1]=r[3];
                }
            }
            uint32_t ah[2][4], al[2][4];
#pragma unroll
            for (int i = 0; i < 2; i++) {
                uint32_t off = (uint32_t)(wm * 32 + i * 16 + am) * ROWB + (kk + ak) * 2;
                ldsm4(ah[i], sb + SM_AHI + off);
                ldsm4(al[i], sb + SM_ALO + off);
            }
#pragma unroll
            for (int i = 0; i < 2; i++)
#pragma unroll
                for (int f = 0; f < 4; f++) {
                    mma16816(acc[i][f], ah[i], bh[f]);
                    mma16816(acc[i][f], ah[i], bl[f]);
                    mma16816(acc[i][f], al[i], bh[f]);
                }
        }
        __syncthreads();
    }

#pragma unroll
    for (int i = 0; i < 2; i++) {
#pragma unroll
        for (int f = 0; f < 4; f++) {
            int row = bm + wm * 32 + i * 16 + (lane >> 2);
            int col = bn + wn * 32 + f * 8 + (lane & 3) * 2;
            float2 bb = make_float2(0.f, 0.f);
            if (HASBIAS) bb = *(const float2*)&bias[(long)z * zBias + col];
            float2 o0, o1;
            o0.x = alpha * acc[i][f][0] + bb.x;
            o0.y = alpha * acc[i][f][1] + bb.y;
            o1.x = alpha * acc[i][f][2] + bb.x;
            o1.y = alpha * acc[i][f][3] + bb.y;
            *(float2*)&C[(long)row * ldc + col] = o0;
            *(float2*)&C[(long)(row + 8) * ldc + col] = o1;
        }
    }
}

// ================= qhat GEMM: A-resident n-loop (K=64 fits SMEM once) ==========
// Per head z: qhat[:, z*512 + :] = 0.125 * qq[:, z*64:(z+1)*64] @ Wk_eff_h [64,512]
// Grid (1, 32, 8). A tile [128x64] loaded once; loop 8 n-tiles of B with
// register prefetch. A traffic /8 vs the generic kernel.
__global__ void __launch_bounds__(256, 2)
qhat_gemm(const float* __restrict__ qq, const float* __restrict__ Wk,
          float* __restrict__ qhat)
{
    extern __shared__ __align__(16) char sm[];
    uint32_t sb = smem_u32(sm);

    int z = blockIdx.z;
    int bm = blockIdx.y * 128;
    const float* B = Wk + (long)z * Dd * Ee;     // [64, 512]
    float* C = qhat + (long)z * Ee;              // row stride Hh*Ee = 4096

    int tid = threadIdx.x;
    int wid = tid >> 5;
    int lane = tid & 31;
    int wm = wid & 3;
    int wn = wid >> 2;

    int am = ((lane >> 3) & 1) * 8 + (lane & 7);
    int ak = (lane >> 4) * 8;
    int bkr = ((lane >> 3) & 1) * 8 + (lane & 7);
    int bnc = (lane >> 4) * 8;

    // ---- A tile: 128 rows x 64 k (cols z*64..z*64+63 of qq), loaded once ----
#pragma unroll
    for (int i = 0; i < 8; i++) {
        int p = tid + i * 256;
        int row = p >> 4;
        int c4 = p & 15;
        float4 v = *(const float4*)&qq[(long)(bm + row) * Ee + z * Dd + c4 * 4];
        uint2 hi, lo;
        split4(v, hi, lo);
        uint32_t off = row * ROWB + c4 * 8;
        *(uint2*)(sm + SM_AHI + off) = hi;
        *(uint2*)(sm + SM_ALO + off) = lo;
    }

    // prefetch first B tile (64 k-rows x 64 n-cols), 4 float4 per thread
    int brow0 = tid >> 4, bc4 = tid & 15;
    float4 pb[4];
#pragma unroll
    for (int i = 0; i < 4; i++) {
        int p = tid + i * 256;
        int row = p >> 4;
        int c4 = p & 15;
        pb[i] = *(const float4*)&B[(long)row * Ee + 0 + c4 * 4];
    }
    (void)brow0; (void)bc4;
    __syncthreads();

    for (int nt = 0; nt < 8; nt++) {
        // store current B tile as [k][n] (trans-read path)
#pragma unroll
        for (int i = 0; i < 4; i++) {
            int p = tid + i * 256;
            int row = p >> 4;
            int c4 = p & 15;
            uint2 hi, lo;
            split4(pb[i], hi, lo);
            uint32_t off = row * ROWB + c4 * 8;
            *(uint2*)(sm + SM_BHI + off) = hi;
            *(uint2*)(sm + SM_BLO + off) = lo;
        }
        __syncthreads();

        // prefetch next B tile
        if (nt + 1 < 8) {
#pragma unroll
            for (int i = 0; i < 4; i++) {
                int p = tid + i * 256;
                int row = p >> 4;
                int c4 = p & 15;
                pb[i] = *(const float4*)&B[(long)row * Ee + (nt + 1) * 64 + c4 * 4];
            }
        }

        float acc[2][4][4];
#pragma unroll
        for (int i = 0; i < 2; i++)
#pragma unroll
            for (int f = 0; f < 4; f++)
#pragma unroll
                for (int r = 0; r < 4; r++) acc[i][f][r] = 0.f;

#pragma unroll
        for (int ks = 0; ks < 4; ks++) {
            int kk = ks * 16;
            uint32_t bh[4][2], bl[4][2];
#pragma unroll
            for (int g = 0; g < 2; g++) {
                uint32_t r[4];
                uint32_t off = (uint32_t)(kk + bkr) * ROWB + (wn * 32 + g * 16 + bnc) * 2;
                ldsm4t(r, sb + SM_BHI + off);
                bh[g*2][0]=r[0]; bh[g*2][1]=r[1]; bh[g*2+1][0]=r[2]; bh[g*2+1][1]=r[3];
                ldsm4t(r, sb + SM_BLO + off);
                bl[g*2][0]=r[0]; bl[g*2][1]=r[1]; bl[g*2+1][0]=r[2]; bl[g*2+1][1]=r[3];
            }
            uint32_t ah[2][4], al[2][4];
#pragma unroll
            for (int i = 0; i < 2; i++) {
                uint32_t off = (uint32_t)(wm * 32 + i * 16 + am) * ROWB + (kk + ak) * 2;
                ldsm4(ah[i], sb + SM_AHI + off);
                ldsm4(al[i], sb + SM_ALO + off);
            }
#pragma unroll
            for (int i = 0; i < 2; i++)
#pragma unroll
                for (int f = 0; f < 4; f++) {
                    mma16816(acc[i][f], ah[i], bh[f]);
                    mma16816(acc[i][f], ah[i], bl[f]);
                    mma16816(acc[i][f], al[i], bh[f]);
                }
        }

        // epilogue for this n-tile
#pragma unroll
        for (int i = 0; i < 2; i++) {
#pragma unroll
            for (int f = 0; f < 4; f++) {
                int row = bm + wm * 32 + i * 16 + (lane >> 2);
                int col = nt * 64 + wn * 32 + f * 8 + (lane & 3) * 2;
                float2 o0, o1;
                o0.x = 0.125f * acc[i][f][0];
                o0.y = 0.125f * acc[i][f][1];
                o1.x = 0.125f * acc[i][f][2];
                o1.y = 0.125f * acc[i][f][3];
                *(float2*)&C[(long)row * (Hh * Ee) + col] = o0;
                *(float2*)&C[(long)(row + 8) * (Hh * Ee) + col] = o1;
            }
        }
        __syncthreads();   // B SMEM overwritten next iteration
    }
}

// ---------------- bias folding: bq_eff, bv_eff, bo_eff -----------------
__global__ void bias_fold(const float* __restrict__ ipw, const float* __restrict__ ipb,
                          const float* __restrict__ bq,  const float* __restrict__ bv,
                          const float* __restrict__ out_w, const float* __restrict__ mob,
                          const float* __restrict__ out_b)
{
    int gw = (blockIdx.x * blockDim.x + threadIdx.x) >> 5;
    int lane = threadIdx.x & 31;
    if (gw >= 3 * Ee) return;
    int which = gw / Ee, i = gw % Ee;
    const float* rowp;
    const float* vec;
    float add;
    if (which == 0)      { rowp = ipw + (long)i * Ee;            vec = bq;  add = ipb[i]; }
    else if (which == 1) { rowp = ipw + (long)(2 * Ee + i) * Ee; vec = bv;  add = ipb[2 * Ee + i]; }
    else                 { rowp = out_w + (long)i * Ee;          vec = mob; add = out_b[i]; }
    float s = 0.f;
    for (int k = lane; k < Ee; k += 32) s += rowp[k] * vec[k];
#pragma unroll
    for (int o = 16; o; o >>= 1) s += __shfl_xor_sync(0xffffffffu, s, o);
    if (lane == 0) g_beff[gw] = s + add;
}

// ---------------- segment starts (batch sorted, all B present) -----------------
__global__ void segstart_kernel(const int* __restrict__ batch)
{
    int n = blockIdx.x * 256 + threadIdx.x;
    if (n < Nn) {
        int b = batch[n];
        if (n == 0 || batch[n - 1] != b) g_segstart[b] = n;
    }
    if (n == 0) g_segstart[Bb] = Nn;
}

// ================= fused segment attention (unchanged from R4, proven) ==========
__global__ void __launch_bounds__(256) fused_attn_kernel(const float* __restrict__ X)
{
    __shared__ float qsh[4096];        // qhat[b]  [8][512]
    __shared__ float lgsh[32][9];      // chunk logits (padded)
    __shared__ float psh[32][8];       // chunk p values
    __shared__ float st_m[8], st_Z[8], st_f[8];

    int b = blockIdx.x;
    int t = threadIdx.x;
    int w = t >> 5, lane = t & 31;
    int s0 = g_segstart[b], e0 = g_segstart[b + 1];

    {
        const float4* src = (const float4*)(g_qhat + (size_t)b * (Hh * Ee));
        float4* dst = (float4*)qsh;
#pragma unroll
        for (int i = 0; i < 4; i++) dst[t + 256 * i] = src[t + 256 * i];
    }
    if (t < 8) { st_m[t] = -1e30f; st_Z[t] = 0.f; }
    __syncthreads();

    float acc[8][2];
#pragma unroll
    for (int h = 0; h < 8; h++) { acc[h][0] = 0.f; acc[h][1] = 0.f; }

    for (int base = s0; base < e0; base += 32) {
        int cnt = min(32, e0 - base);

        // ---- phase A: logits, 4 nodes per warp ----
        {
            int nb = base + 4 * w;
            float4 xv[4][4];
#pragma unroll
            for (int j = 0; j < 4; j++) {
                int n = nb + j;
                if (n < e0) {
                    const float4* xr = (const float4*)(X + (size_t)n * Ee);
#pragma unroll
                    for (int i = 0; i < 4; i++) xv[j][i] = xr[lane + 32 * i];
                } else {
#pragma unroll
                    for (int i = 0; i < 4; i++) xv[j][i] = make_float4(0.f, 0.f, 0.f, 0.f);
                }
            }
#pragma unroll
            for (int h = 0; h < 8; h++) {
                const float4* q = (const float4*)qsh + h * 128;
                float4 q0 = q[lane], q1 = q[lane + 32], q2 = q[lane + 64], q3 = q[lane + 96];
                float s[4];
#pragma unroll
                for (int j = 0; j < 4; j++) {
                    float v;
                    v  = xv[j][0].x * q0.x + xv[j][0].y * q0.y + xv[j][0].z * q0.z + xv[j][0].w * q0.w;
                    v += xv[j][1].x * q1.x + xv[j][1].y * q1.y + xv[j][1].z * q1.z + xv[j][1].w * q1.w;
                    v += xv[j][2].x * q2.x + xv[j][2].y * q2.y + xv[j][2].z * q2.z + xv[j][2].w * q2.w;
                    v += xv[j][3].x * q3.x + xv[j][3].y * q3.y + xv[j][3].z * q3.z + xv[j][3].w * q3.w;
                    s[j] = v;
                }
#pragma unroll
                for (int o = 16; o; o >>= 1) {
#pragma unroll
                    for (int j = 0; j < 4; j++) s[j] += __shfl_xor_sync(0xffffffffu, s[j], o);
                }
                if (lane == 0) {
#pragma unroll
                    for (int j = 0; j < 4; j++)
                        lgsh[4 * w + j][h] = (nb + j < e0) ? s[j] : -1e30f;
                }
            }
        }
        __syncthreads();

        // ---- stats: warp w handles head w ----
        if (w < 8) {
            float v = (lane < cnt) ? lgsh[lane][w] : -1e30f;
            float mx = v;
#pragma unroll
            for (int o = 16; o; o >>= 1) mx = fmaxf(mx, __shfl_xor_sync(0xffffffffu, mx, o));
            float mo = st_m[w];
            float mn = fmaxf(mo, mx);
            float p = (lane < cnt) ? __expf(v - mn) : 0.f;
            psh[lane][w] = p;
            float ssum = p;
#pragma unroll
            for (int o = 16; o; o >>= 1) ssum += __shfl_xor_sync(0xffffffffu, ssum, o);
            if (lane == 0) {
                float f = __expf(mo - mn);
                st_f[w] = f;
                st_m[w] = mn;
                st_Z[w] = st_Z[w] * f + ssum;
            }
        }
        __syncthreads();

        // ---- rescale + phase C ----
#pragma unroll
        for (int h = 0; h < 8; h++) {
            float f = st_f[h];
            acc[h][0] *= f;
            acc[h][1] *= f;
        }
        int i = 0;
        for (; i + 4 <= cnt; i += 4) {
            float2 x0 = *(const float2*)&X[(size_t)(base + i + 0) * Ee + 2 * t];
            float2 x1 = *(const float2*)&X[(size_t)(base + i + 1) * Ee + 2 * t];
            float2 x2 = *(const float2*)&X[(size_t)(base + i + 2) * Ee + 2 * t];
            float2 x3 = *(const float2*)&X[(size_t)(base + i + 3) * Ee + 2 * t];
#pragma unroll
            for (int j = 0; j < 4; j++) {
                float2 x = (j == 0) ? x0 : (j == 1) ? x1 : (j == 2) ? x2 : x3;
                float4 p0 = *(const float4*)&psh[i + j][0];
                float4 p1 = *(const float4*)&psh[i + j][4];
                float pw[8] = {p0.x, p0.y, p0.z, p0.w, p1.x, p1.y, p1.z, p1.w};
#pragma unroll
                for (int h = 0; h < 8; h++) {
                    acc[h][0] += pw[h] * x.x;
                    acc[h][1] += pw[h] * x.y;
                }
            }
        }
        for (; i < cnt; i++) {
            float2 x = *(const float2*)&X[(size_t)(base + i) * Ee + 2 * t];
            float4 p0 = *(const float4*)&psh[i][0];
            float4 p1 = *(const float4*)&psh[i][4];
            float pw[8] = {p0.x, p0.y, p0.z, p0.w, p1.x, p1.y, p1.z, p1.w};
#pragma unroll
            for (int h = 0; h < 8; h++) {
                acc[h][0] += pw[h] * x.x;
                acc[h][1] += pw[h] * x.y;
            }
        }
        __syncthreads();
    }

    float rZ[8];
#pragma unroll
    for (int h = 0; h < 8; h++) rZ[h] = 1.f / st_Z[h];
#pragma unroll
    for (int h = 0; h < 8; h++) {
        float2 o = make_float2(acc[h][0] * rZ[h], acc[h][1] * rZ[h]);
        *(float2*)&g_xw[((size_t)b * Hh + h) * Ee + 2 * t] = o;
    }
}

// ---------------- LayerNorm over rows of outbuf -> d_out -----------------
__global__ void __launch_bounds__(256) ln_kernel(const float* __restrict__ lng,
                                                 const float* __restrict__ lnb,
                                                 float* __restrict__ out)
{
    int b = blockIdx.x;
    int t = threadIdx.x;
    float v0 = g_outbuf[(long)b * Ee + t];
    float v1 = g_outbuf[(long)b * Ee + t + 256];
    float s = v0 + v1;
    float q = v0 * v0 + v1 * v1;
#pragma unroll
    for (int o = 16; o; o >>= 1) {
        s += __shfl_xor_sync(0xffffffffu, s, o);
        q += __shfl_xor_sync(0xffffffffu, q, o);
    }
    __shared__ float ss[8], qs[8];
    __shared__ float mu_s, r_s;
    int wid = t >> 5, lane = t & 31;
    if (lane == 0) { ss[wid] = s; qs[wid] = q; }
    __syncthreads();
    if (t == 0) {
        float S = 0.f, Q = 0.f;
#pragma unroll
        for (int i = 0; i < 8; i++) { S += ss[i]; Q += qs[i]; }
        float mu = S / (float)Ee;
        float var = Q / (float)Ee - mu * mu;
        mu_s = mu;
        r_s = 1.f / sqrtf(var + 1e-5f);
    }
    __syncthreads();
    float mu = mu_s, r = r_s;
    out[(long)b * Ee + t]       = (v0 - mu) * r * lng[t]       + lnb[t];
    out[(long)b * Ee + t + 256] = (v1 - mu) * r * lng[t + 256] + lnb[t + 256];
}

// ---------------- launch -----------------
extern "C" void kernel_launch(void* const* d_in, const int* in_sizes, int n_in,
                              void* d_out, int out_size)
{
    (void)in_sizes; (void)n_in; (void)out_size;
    const float* X        = (const float*)d_in[0];   // node_features [N,E]
    const float* scaffold = (const float*)d_in[1];   // [B,E]
    const float* Wq       = (const float*)d_in[2];
    const float* bq       = (const float*)d_in[3];
    const float* Wk       = (const float*)d_in[4];
    const float* Wv       = (const float*)d_in[6];
    const float* bv       = (const float*)d_in[7];
    const float* ipw      = (const float*)d_in[8];   // in_proj_w [3E,E]
    const float* ipb      = (const float*)d_in[9];
    const float* mow      = (const float*)d_in[10];  // mha_out_w
    const float* mob      = (const float*)d_in[11];
    const float* ow       = (const float*)d_in[12];  // out_w
    const float* ob       = (const float*)d_in[13];
    const float* lng      = (const float*)d_in[14];
    const float* lnb      = (const float*)d_in[15];
    const int*   batch    = (const int*)d_in[16];

    void* p;
    cudaGetSymbolAddress(&p, g_Acat);   float* Acat   = (float*)p;
    cudaGetSymbolAddress(&p, g_Bcat);   float* Bcat   = (float*)p;
    cudaGetSymbolAddress(&p, g_Weff);   float* Weff   = (float*)p;
    cudaGetSymbolAddress(&p, g_beff);   float* beff   = (float*)p;
    cudaGetSymbolAddress(&p, g_qq);     float* qq     = (float*)p;
    cudaGetSymbolAddress(&p, g_qhat);   float* qhat   = (float*)p;
    cudaGetSymbolAddress(&p, g_xw);     float* xw     = (float*)p;
    cudaGetSymbolAddress(&p, g_pooled); float* pooled = (float*)p;
    cudaGetSymbolAddress(&p, g_outbuf); float* outbuf = (float*)p;

    cudaFuncSetAttribute(tcgemm<false, false>,
                         cudaFuncAttributeMaxDynamicSharedMemorySize, SM_TOTAL);
    cudaFuncSetAttribute(tcgemm<true, true>,
                         cudaFuncAttributeMaxDynamicSharedMemorySize, SM_TOTAL);
    cudaFuncSetAttribute(qhat_gemm,
                         cudaFuncAttributeMaxDynamicSharedMemorySize, SM_TOTAL);

    // concat fold operands: Acat=[Wiq;Wik;Wiv;out_w], Bcat=[Wq;Wk;Wv;mha_out_w]
    cudaMemcpyAsync(Acat,          ipw, (size_t)3 * EE * sizeof(float), cudaMemcpyDeviceToDevice, 0);
    cudaMemcpyAsync(Acat + 3 * EE, ow,  (size_t)EE * sizeof(float),     cudaMemcpyDeviceToDevice, 0);
    cudaMemcpyAsync(Bcat,          Wq,  (size_t)EE * sizeof(float),     cudaMemcpyDeviceToDevice, 0);
    cudaMemcpyAsync(Bcat + EE,     Wk,  (size_t)EE * sizeof(float),     cudaMemcpyDeviceToDevice, 0);
    cudaMemcpyAsync(Bcat + 2 * EE, Wv,  (size_t)EE * sizeof(float),     cudaMemcpyDeviceToDevice, 0);
    cudaMemcpyAsync(Bcat + 3 * EE, mow, (size_t)EE * sizeof(float),     cudaMemcpyDeviceToDevice, 0);

    // fold: Weff[z] = Acat[z] @ Bcat[z]  (z = q,k,v,o), 512x512x512 each (NN)
    tcgemm<false, false><<<dim3(8, 4, 4), 256, SM_TOTAL>>>(Acat, Bcat, Weff, nullptr,
        512, 512, 512, 512, (long)EE, (long)EE, (long)EE, 0, 1.f);

    bias_fold<<<192, 256>>>(ipw, ipb, bq, bv, ow, mob, ob);

    // qq = scaffold @ Wq_eff^T + bq_eff   [4096,512,512] NT
    tcgemm<true, true><<<dim3(8, 32, 1), 256, SM_TOTAL>>>(scaffold, Weff, qq, beff,
        512, Ee, Ee, Ee, 0, 0, 0, 0, 1.f);

    // qhat[b,h,:] = scale * qq[b,h,:] @ Wk_eff_h   (A-resident n-loop kernel)
    qhat_gemm<<<dim3(1, 32, 8), 256, SM_TOTAL>>>(qq, Weff + EE, qhat);

    segstart_kernel<<<Nn / 256, 256>>>(batch);

    // fused logits + online softmax + weighted sum
    fused_attn_kernel<<<Bb, 256>>>(X);

    // pooled[b, h*D+:] = xw[b,h,:] @ Wv_eff_h^T + bv_eff   [4096,64,512] NT x 8 heads
    tcgemm<true, true><<<dim3(1, 32, 8), 256, SM_TOTAL>>>(xw, Weff + 2 * EE, pooled, beff + Ee,
        512, Hh * Ee, Ee, Ee, (long)Ee, (long)Dd * Ee, (long)Dd, Dd, 1.f);

    // out = pooled @ Wo_eff^T + bo_eff   [4096,512,512] NT
    tcgemm<true, true><<<dim3(8, 32, 1), 256, SM_TOTAL>>>(pooled, Weff + 3 * EE, outbuf, beff + 2 * Ee,
        512, Ee, Ee, Ee, 0, 0, 0, 0, 1.f);

    ln_kernel<<<Bb, 256>>>(lng, lnb, (float*)d_out);
}

// round 8
// speedup vs baseline: 1.2383x; 1.1929x over previous
#include <cuda_runtime.h>
#include <cuda_bf16.h>
#include <math.h>
#include <stdint.h>

#define Nn 131072
#define Bb 4096
#define Ee 512
#define Hh 8
#define Dd 64
#define EE (Ee*Ee)

// ---------------- scratch (device globals; no allocation allowed) ----------------
__device__ __align__(16) float g_Acat[4*EE];
__device__ __align__(16) float g_Bcat[4*EE];
__device__ __align__(16) float g_Weff[4*EE];          // [Wq_eff; Wk_eff; Wv_eff; Wo_eff]
__device__ __align__(16) float g_beff[3*Ee];          // [bq_eff; bv_eff; bo_eff]
__device__ __align__(16) float g_qq[Bb*Ee];
__device__ __align__(16) float g_qhat[(size_t)Bb*Hh*Ee];
__device__ int   g_segstart[Bb+1];
__device__ __align__(16) float g_xw[(size_t)Bb*Hh*Ee];
__device__ __align__(16) float g_pooled[Bb*Ee];
__device__ __align__(16) float g_outbuf[Bb*Ee];

// ================= mma.sync helpers (compute_103 baseline features) =============
__device__ __forceinline__ uint32_t smem_u32(const void* p) {
    uint32_t a;
    asm("{ .reg .u64 t; cvta.to.shared.u64 t, %1; cvt.u32.u64 %0, t; }" : "=r"(a) : "l"(p));
    return a;
}

__device__ __forceinline__ void ldsm4(uint32_t* r, uint32_t addr) {
    asm volatile("ldmatrix.sync.aligned.m8n8.x4.shared.b16 {%0,%1,%2,%3}, [%4];"
        : "=r"(r[0]), "=r"(r[1]), "=r"(r[2]), "=r"(r[3]) : "r"(addr));
}
__device__ __forceinline__ void ldsm4t(uint32_t* r, uint32_t addr) {
    asm volatile("ldmatrix.sync.aligned.m8n8.x4.trans.shared.b16 {%0,%1,%2,%3}, [%4];"
        : "=r"(r[0]), "=r"(r[1]), "=r"(r[2]), "=r"(r[3]) : "r"(addr));
}
__device__ __forceinline__ void mma16816(float* c, const uint32_t* a, const uint32_t* b) {
    asm volatile("mma.sync.aligned.m16n8k16.row.col.f32.bf16.bf16.f32 "
        "{%0,%1,%2,%3}, {%4,%5,%6,%7}, {%8,%9}, {%0,%1,%2,%3};"
        : "+f"(c[0]), "+f"(c[1]), "+f"(c[2]), "+f"(c[3])
        : "r"(a[0]), "r"(a[1]), "r"(a[2]), "r"(a[3]), "r"(b[0]), "r"(b[1]));
}

// ---------- fp32 -> bf16 hi/lo split ----------
__device__ __forceinline__ void split4(float4 v, uint2& hi, uint2& lo) {
    __nv_bfloat162 h0 = __floats2bfloat162_rn(v.x, v.y);
    __nv_bfloat162 h1 = __floats2bfloat162_rn(v.z, v.w);
    float2 f0 = __bfloat1622float2(h0);
    float2 f1 = __bfloat1622float2(h1);
    __nv_bfloat162 l0 = __floats2bfloat162_rn(v.x - f0.x, v.y - f0.y);
    __nv_bfloat162 l1 = __floats2bfloat162_rn(v.z - f1.x, v.w - f1.y);
    hi.x = *(uint32_t*)&h0; hi.y = *(uint32_t*)&h1;
    lo.x = *(uint32_t*)&l0; lo.y = *(uint32_t*)&l1;
}

// ================= HMMA GEMM (exact R3/R4 version, proven) =================
#define ROWB 144
#define SM_AHI 0
#define SM_ALO 18432
#define SM_BHI 36864
#define SM_BLO 46080
#define SM_TOTAL 55296

template<bool TRANSB, bool HASBIAS>
__global__ void __launch_bounds__(256, 2)
tcgemm(const float* __restrict__ A, const float* __restrict__ B,
       float* __restrict__ C, const float* __restrict__ bias,
       int K, int lda, int ldb, int ldc,
       long zA, long zB, long zC, int zBias, float alpha)
{
    extern __shared__ __align__(16) char sm[];
    uint32_t sb = smem_u32(sm);

    int z = blockIdx.z;
    A += (long)z * zA;
    B += (long)z * zB;
    C += (long)z * zC;
    int bm = blockIdx.y * 128;
    int bn = blockIdx.x * 64;
    int tid = threadIdx.x;
    int wid = tid >> 5;
    int lane = tid & 31;
    int wm = wid & 3;
    int wn = wid >> 2;

    float acc[2][4][4];
#pragma unroll
    for (int i = 0; i < 2; i++)
#pragma unroll
        for (int f = 0; f < 4; f++)
#pragma unroll
            for (int r = 0; r < 4; r++) acc[i][f][r] = 0.f;

    int am = ((lane >> 3) & 1) * 8 + (lane & 7);
    int ak = (lane >> 4) * 8;
    int bnr = ((lane >> 4) & 1) * 8 + (lane & 7);
    int bkc = ((lane >> 3) & 1) * 8;
    int bkr = ((lane >> 3) & 1) * 8 + (lane & 7);
    int bnc = (lane >> 4) * 8;

    const int nch = K / 64;
    for (int ch = 0; ch < nch; ch++) {
        int k0 = ch * 64;

#pragma unroll
        for (int i = 0; i < 8; i++) {
            int p = tid + i * 256;
            int row = p >> 4;
            int c4 = p & 15;
            float4 v = *(const float4*)&A[(long)(bm + row) * lda + k0 + c4 * 4];
            uint2 hi, lo;
            split4(v, hi, lo);
            uint32_t off = row * ROWB + c4 * 8;
            *(uint2*)(sm + SM_AHI + off) = hi;
            *(uint2*)(sm + SM_ALO + off) = lo;
        }
#pragma unroll
        for (int i = 0; i < 4; i++) {
            int p = tid + i * 256;
            int row = p >> 4;
            int c4 = p & 15;
            const float* src = TRANSB ? &B[(long)(bn + row) * ldb + k0 + c4 * 4]
                                      : &B[(long)(k0 + row) * ldb + bn + c4 * 4];
            float4 v = *(const float4*)src;
            uint2 hi, lo;
            split4(v, hi, lo);
            uint32_t off = row * ROWB + c4 * 8;
            *(uint2*)(sm + SM_BHI + off) = hi;
            *(uint2*)(sm + SM_BLO + off) = lo;
        }
        __syncthreads();

#pragma unroll
        for (int ks = 0; ks < 4; ks++) {
            int kk = ks * 16;
            uint32_t bh[4][2], bl[4][2];
#pragma unroll
            for (int g = 0; g < 2; g++) {
                uint32_t r[4];
                if (TRANSB) {
                    uint32_t off = (uint32_t)(wn * 32 + g * 16 + bnr) * ROWB + (kk + bkc) * 2;
                    ldsm4(r, sb + SM_BHI + off);
                    bh[g*2][0]=r[0]; bh[g*2][1]=r[1]; bh[g*2+1][0]=r[2]; bh[g*2+1][1]=r[3];
                    ldsm4(r, sb + SM_BLO + off);
                    bl[g*2][0]=r[0]; bl[g*2][1]=r[1]; bl[g*2+1][0]=r[2]; bl[g*2+1][1]=r[3];
                } else {
                    uint32_t off = (uint32_t)(kk + bkr) * ROWB + (wn * 32 + g * 16 + bnc) * 2;
                    ldsm4t(r, sb + SM_BHI + off);
                    bh[g*2][0]=r[0]; bh[g*2][1]=r[1]; bh[g*2+1][0]=r[2]; bh[g*2+1][1]=r[3];
                    ldsm4t(r, sb + SM_BLO + off);
                    bl[g*2][0]=r[0]; bl[g*2][1]=r[1]; bl[g*2+1][0]=r[2]; bl[g*2+1][1]=r[3];
                }
            }
            uint32_t ah[2][4], al[2][4];
#pragma unroll
            for (int i = 0; i < 2; i++) {
                uint32_t off = (uint32_t)(wm * 32 + i * 16 + am) * ROWB + (kk + ak) * 2;
                ldsm4(ah[i], sb + SM_AHI + off);
                ldsm4(al[i], sb + SM_ALO + off);
            }
#pragma unroll
            for (int i = 0; i < 2; i++)
#pragma unroll
                for (int f = 0; f < 4; f++) {
                    mma16816(acc[i][f], ah[i], bh[f]);
                    mma16816(acc[i][f], ah[i], bl[f]);
                    mma16816(acc[i][f], al[i], bh[f]);
                }
        }
        __syncthreads();
    }

#pragma unroll
    for (int i = 0; i < 2; i++) {
#pragma unroll
        for (int f = 0; f < 4; f++) {
            int row = bm + wm * 32 + i * 16 + (lane >> 2);
            int col = bn + wn * 32 + f * 8 + (lane & 3) * 2;
            float2 bb = make_float2(0.f, 0.f);
            if (HASBIAS) bb = *(const float2*)&bias[(long)z * zBias + col];
            float2 o0, o1;
            o0.x = alpha * acc[i][f][0] + bb.x;
            o0.y = alpha * acc[i][f][1] + bb.y;
            o1.x = alpha * acc[i][f][2] + bb.x;
            o1.y = alpha * acc[i][f][3] + bb.y;
            *(float2*)&C[(long)row * ldc + col] = o0;
            *(float2*)&C[(long)(row + 8) * ldc + col] = o1;
        }
    }
}

// ================= qhat GEMM: A-resident n-loop (unchanged from R7) ==========
__global__ void __launch_bounds__(256, 2)
qhat_gemm(const float* __restrict__ qq, const float* __restrict__ Wk,
          float* __restrict__ qhat)
{
    extern __shared__ __align__(16) char sm[];
    uint32_t sb = smem_u32(sm);

    int z = blockIdx.z;
    int bm = blockIdx.y * 128;
    const float* B = Wk + (long)z * Dd * Ee;
    float* C = qhat + (long)z * Ee;

    int tid = threadIdx.x;
    int lane = tid & 31;
    int wid = tid >> 5;
    int wm = wid & 3;
    int wn = wid >> 2;

    int am = ((lane >> 3) & 1) * 8 + (lane & 7);
    int ak = (lane >> 4) * 8;
    int bkr = ((lane >> 3) & 1) * 8 + (lane & 7);
    int bnc = (lane >> 4) * 8;

#pragma unroll
    for (int i = 0; i < 8; i++) {
        int p = tid + i * 256;
        int row = p >> 4;
        int c4 = p & 15;
        float4 v = *(const float4*)&qq[(long)(bm + row) * Ee + z * Dd + c4 * 4];
        uint2 hi, lo;
        split4(v, hi, lo);
        uint32_t off = row * ROWB + c4 * 8;
        *(uint2*)(sm + SM_AHI + off) = hi;
        *(uint2*)(sm + SM_ALO + off) = lo;
    }

    float4 pb[4];
#pragma unroll
    for (int i = 0; i < 4; i++) {
        int p = tid + i * 256;
        int row = p >> 4;
        int c4 = p & 15;
        pb[i] = *(const float4*)&B[(long)row * Ee + 0 + c4 * 4];
    }
    __syncthreads();

    for (int nt = 0; nt < 8; nt++) {
#pragma unroll
        for (int i = 0; i < 4; i++) {
            int p = tid + i * 256;
            int row = p >> 4;
            int c4 = p & 15;
            uint2 hi, lo;
            split4(pb[i], hi, lo);
            uint32_t off = row * ROWB + c4 * 8;
            *(uint2*)(sm + SM_BHI + off) = hi;
            *(uint2*)(sm + SM_BLO + off) = lo;
        }
        __syncthreads();

        if (nt + 1 < 8) {
#pragma unroll
            for (int i = 0; i < 4; i++) {
                int p = tid + i * 256;
                int row = p >> 4;
                int c4 = p & 15;
                pb[i] = *(const float4*)&B[(long)row * Ee + (nt + 1) * 64 + c4 * 4];
            }
        }

        float acc[2][4][4];
#pragma unroll
        for (int i = 0; i < 2; i++)
#pragma unroll
            for (int f = 0; f < 4; f++)
#pragma unroll
                for (int r = 0; r < 4; r++) acc[i][f][r] = 0.f;

#pragma unroll
        for (int ks = 0; ks < 4; ks++) {
            int kk = ks * 16;
            uint32_t bh[4][2], bl[4][2];
#pragma unroll
            for (int g = 0; g < 2; g++) {
                uint32_t r[4];
                uint32_t off = (uint32_t)(kk + bkr) * ROWB + (wn * 32 + g * 16 + bnc) * 2;
                ldsm4t(r, sb + SM_BHI + off);
                bh[g*2][0]=r[0]; bh[g*2][1]=r[1]; bh[g*2+1][0]=r[2]; bh[g*2+1][1]=r[3];
                ldsm4t(r, sb + SM_BLO + off);
                bl[g*2][0]=r[0]; bl[g*2][1]=r[1]; bl[g*2+1][0]=r[2]; bl[g*2+1][1]=r[3];
            }
            uint32_t ah[2][4], al[2][4];
#pragma unroll
            for (int i = 0; i < 2; i++) {
                uint32_t off = (uint32_t)(wm * 32 + i * 16 + am) * ROWB + (kk + ak) * 2;
                ldsm4(ah[i], sb + SM_AHI + off);
                ldsm4(al[i], sb + SM_ALO + off);
            }
#pragma unroll
            for (int i = 0; i < 2; i++)
#pragma unroll
                for (int f = 0; f < 4; f++) {
                    mma16816(acc[i][f], ah[i], bh[f]);
                    mma16816(acc[i][f], ah[i], bl[f]);
                    mma16816(acc[i][f], al[i], bh[f]);
                }
        }

#pragma unroll
        for (int i = 0; i < 2; i++) {
#pragma unroll
            for (int f = 0; f < 4; f++) {
                int row = bm + wm * 32 + i * 16 + (lane >> 2);
                int col = nt * 64 + wn * 32 + f * 8 + (lane & 3) * 2;
                float2 o0, o1;
                o0.x = 0.125f * acc[i][f][0];
                o0.y = 0.125f * acc[i][f][1];
                o1.x = 0.125f * acc[i][f][2];
                o1.y = 0.125f * acc[i][f][3];
                *(float2*)&C[(long)row * (Hh * Ee) + col] = o0;
                *(float2*)&C[(long)(row + 8) * (Hh * Ee) + col] = o1;
            }
        }
        __syncthreads();
    }
}

// ---------------- bias folding ----------------
__global__ void bias_fold(const float* __restrict__ ipw, const float* __restrict__ ipb,
                          const float* __restrict__ bq,  const float* __restrict__ bv,
                          const float* __restrict__ out_w, const float* __restrict__ mob,
                          const float* __restrict__ out_b)
{
    int gw = (blockIdx.x * blockDim.x + threadIdx.x) >> 5;
    int lane = threadIdx.x & 31;
    if (gw >= 3 * Ee) return;
    int which = gw / Ee, i = gw % Ee;
    const float* rowp;
    const float* vec;
    float add;
    if (which == 0)      { rowp = ipw + (long)i * Ee;            vec = bq;  add = ipb[i]; }
    else if (which == 1) { rowp = ipw + (long)(2 * Ee + i) * Ee; vec = bv;  add = ipb[2 * Ee + i]; }
    else                 { rowp = out_w + (long)i * Ee;          vec = mob; add = out_b[i]; }
    float s = 0.f;
    for (int k = lane; k < Ee; k += 32) s += rowp[k] * vec[k];
#pragma unroll
    for (int o = 16; o; o >>= 1) s += __shfl_xor_sync(0xffffffffu, s, o);
    if (lane == 0) g_beff[gw] = s + add;
}

// ---------------- segment starts ----------------
__global__ void segstart_kernel(const int* __restrict__ batch)
{
    int n = blockIdx.x * 256 + threadIdx.x;
    if (n < Nn) {
        int b = batch[n];
        if (n == 0 || batch[n - 1] != b) g_segstart[b] = n;
    }
    if (n == 0) g_segstart[Bb] = Nn;
}

// ================= fused segment attention, HMMA version =================
// One block per graph b; online softmax over 32-node chunks.
// Phase A (logits = X @ qhat^T) and phase C (acc += X^T @ P) both run on
// mma.sync with bf16 hi/lo emulation. X staged per chunk into SMEM [node][k]
// bf16 hi/lo (row stride 1040B -> conflict-free ldmatrix in both orientations).
// Accumulators live in MMA c-fragments across chunks, rescaled per chunk.
#define XROW   1040
#define F_XHI  0
#define F_XLO  33280
#define F_QHI  66560
#define F_QLO  74880
#define F_LGP  83200
#define F_LGS  91392
#define F_PHI  92544
#define F_PLO  93056
#define F_STM  93568
#define F_STZ  93600
#define F_STF  93632
#define SMEM_FA 93664

__global__ void __launch_bounds__(256)
fused_attn_kernel(const float* __restrict__ X)
{
    extern __shared__ __align__(16) char fsm[];
    uint32_t sb = smem_u32(fsm);

    int b = blockIdx.x;
    int t = threadIdx.x;
    int w = t >> 5, lane = t & 31;
    int gid = lane >> 2, tig = lane & 3;
    int s0 = g_segstart[b], e0 = g_segstart[b + 1];

    float* stm = (float*)(fsm + F_STM);
    float* stz = (float*)(fsm + F_STZ);
    float* stf = (float*)(fsm + F_STF);
    float* lgs = (float*)(fsm + F_LGS);    // [32][9]
    float* lgp = (float*)(fsm + F_LGP);    // [8][256]

    // ---- stage qhat[b] -> bf16 hi/lo SMEM [h][k] ----
#pragma unroll
    for (int i = 0; i < 4; i++) {
        int flat = t + 256 * i;                 // float4 index over [8][128]
        int h = flat >> 7, c4 = flat & 127;
        float4 v = *(const float4*)&g_qhat[(size_t)b * (Hh * Ee) + (size_t)flat * 4];
        (void)h;
        uint2 hi, lo;
        split4(v, hi, lo);
        uint32_t off = (uint32_t)(flat >> 7) * XROW + (uint32_t)c4 * 8;
        *(uint2*)(fsm + F_QHI + off) = hi;
        *(uint2*)(fsm + F_QLO + off) = lo;
    }
    if (t < 8) { stm[t] = -1e30f; stz[t] = 0.f; }
    __syncthreads();

    // per-warp ldmatrix address components
    int am  = ((lane >> 3) & 1) * 8 + (lane & 7);   // non-trans A rows
    int ak  = (lane >> 4) * 8;
    int bkr = ((lane >> 3) & 1) * 8 + (lane & 7);   // trans: k rows
    int bnc = (lane >> 4) * 8;                      // trans: m cols
    int qrow = lane & 7;                            // qhat B ldsm: rows h
    int qc8  = (lane >> 3) * 8;                     // qhat B ldsm: k offset

    // persistent accumulator fragments: 4 m16-tiles (cols w*64 .. w*64+63) x n8(heads)
    float acc[4][4];
#pragma unroll
    for (int mt = 0; mt < 4; mt++)
#pragma unroll
        for (int r = 0; r < 4; r++) acc[mt][r] = 0.f;

    for (int base = s0; base < e0; base += 32) {
        int cnt = min(32, e0 - base);

        // ---- stage X chunk [32 nodes][512] -> bf16 hi/lo, zero-pad tail ----
#pragma unroll
        for (int i = 0; i < 16; i++) {
            int flat = t + 256 * i;             // float4 index over [32][128]
            int node = flat >> 7, c4 = flat & 127;
            float4 v = make_float4(0.f, 0.f, 0.f, 0.f);
            if (node < cnt)
                v = *(const float4*)&X[(size_t)(base + node) * Ee + c4 * 4];
            uint2 hi, lo;
            split4(v, hi, lo);
            uint32_t off = (uint32_t)node * XROW + (uint32_t)c4 * 8;
            *(uint2*)(fsm + F_XHI + off) = hi;
            *(uint2*)(fsm + F_XLO + off) = lo;
        }
        __syncthreads();

        // ---- phase A: warp w computes partial logits over k-slice [w*64, w*64+64) ----
        {
            float lg[2][4];
#pragma unroll
            for (int m = 0; m < 2; m++)
#pragma unroll
                for (int r = 0; r < 4; r++) lg[m][r] = 0.f;

            int ks0 = w * 64;
#pragma unroll
            for (int kb = 0; kb < 2; kb++) {
                int kbase = ks0 + kb * 32;
                uint32_t rq[4];
                uint32_t qoff = (uint32_t)qrow * XROW + (uint32_t)(kbase + qc8) * 2;
                uint32_t bqh[2][2], bql[2][2];
                ldsm4(rq, sb + F_QHI + qoff);
                bqh[0][0]=rq[0]; bqh[0][1]=rq[1]; bqh[1][0]=rq[2]; bqh[1][1]=rq[3];
                ldsm4(rq, sb + F_QLO + qoff);
                bql[0][0]=rq[0]; bql[0][1]=rq[1]; bql[1][0]=rq[2]; bql[1][1]=rq[3];
#pragma unroll
                for (int ks = 0; ks < 2; ks++) {
                    int kk = kbase + ks * 16;
                    uint32_t ah[2][4], al[2][4];
#pragma unroll
                    for (int m = 0; m < 2; m++) {
                        uint32_t aoff = (uint32_t)(m * 16 + am) * XROW + (uint32_t)(kk + ak) * 2;
                        ldsm4(ah[m], sb + F_XHI + aoff);
                        ldsm4(al[m], sb + F_XLO + aoff);
                    }
#pragma unroll
                    for (int m = 0; m < 2; m++) {
                        mma16816(lg[m], ah[m], bqh[ks]);
                        mma16816(lg[m], ah[m], bql[ks]);
                        mma16816(lg[m], al[m], bqh[ks]);
                    }
                }
            }
            // store partial logits: c-frag value (node = m*16 + gid(+8), head = 2*tig(+1))
            float* lp = lgp + w * 256;
#pragma unroll
            for (int m = 0; m < 2; m++) {
                lp[(m * 16 + gid) * 8 + 2 * tig]     = lg[m][0];
                lp[(m * 16 + gid) * 8 + 2 * tig + 1] = lg[m][1];
                lp[(m * 16 + gid + 8) * 8 + 2 * tig]     = lg[m][2];
                lp[(m * 16 + gid + 8) * 8 + 2 * tig + 1] = lg[m][3];
            }
        }
        __syncthreads();

        // ---- sum 8 partials: thread t -> (node=t>>3, h=t&7) ----
        {
            float s = 0.f;
#pragma unroll
            for (int w2 = 0; w2 < 8; w2++) s += lgp[w2 * 256 + t];
            lgs[(t >> 3) * 9 + (t & 7)] = s;
        }
        __syncthreads();

        // ---- stats: warp w handles head w; online max/Z; p -> bf16 hi/lo ----
        {
            float v = (lane < cnt) ? lgs[lane * 9 + w] : -1e30f;
            float mx = v;
#pragma unroll
            for (int o = 16; o; o >>= 1) mx = fmaxf(mx, __shfl_xor_sync(0xffffffffu, mx, o));
            float mo = stm[w];
            float mn = fmaxf(mo, mx);
            float p = (lane < cnt) ? __expf(v - mn) : 0.f;
            __nv_bfloat16 ph = __float2bfloat16(p);
            __nv_bfloat16 pl = __float2bfloat16(p - __bfloat162float(ph));
            ((__nv_bfloat16*)(fsm + F_PHI))[lane * 8 + w] = ph;
            ((__nv_bfloat16*)(fsm + F_PLO))[lane * 8 + w] = pl;
            float ssum = p;
#pragma unroll
            for (int o = 16; o; o >>= 1) ssum += __shfl_xor_sync(0xffffffffu, ssum, o);
            if (lane == 0) {
                float f = __expf(mo - mn);
                stf[w] = f;
                stm[w] = mn;
                stz[w] = stz[w] * f + ssum;
            }
        }
        __syncthreads();

        // ---- phase C: rescale acc, then acc += X^T[cols x nodes] @ P[nodes x heads] ----
        {
            float f0 = stf[2 * tig];
            float f1 = stf[2 * tig + 1];
#pragma unroll
            for (int mt = 0; mt < 4; mt++) {
                acc[mt][0] *= f0; acc[mt][1] *= f1;
                acc[mt][2] *= f0; acc[mt][3] *= f1;
            }
            // P b-frags: trans ldsm on [node][h] (16B rows): k32 x n8 in one ldsm4
            uint32_t rp[4];
            uint32_t bph[2][2], bpl[2][2];
            ldsm4t(rp, sb + F_PHI + (uint32_t)lane * 16);
            bph[0][0]=rp[0]; bph[0][1]=rp[1]; bph[1][0]=rp[2]; bph[1][1]=rp[3];
            ldsm4t(rp, sb + F_PLO + (uint32_t)lane * 16);
            bpl[0][0]=rp[0]; bpl[0][1]=rp[1]; bpl[1][0]=rp[2]; bpl[1][1]=rp[3];

#pragma unroll
            for (int ks = 0; ks < 2; ks++) {
#pragma unroll
                for (int mt = 0; mt < 4; mt++) {
                    uint32_t aoff = (uint32_t)(ks * 16 + bkr) * XROW
                                  + (uint32_t)(w * 64 + mt * 16 + bnc) * 2;
                    uint32_t ra[4], rl[4];
                    ldsm4t(ra, sb + F_XHI + aoff);
                    ldsm4t(rl, sb + F_XLO + aoff);
                    uint32_t ah[4] = {ra[0], ra[2], ra[1], ra[3]};   // a0,a1,a2,a3
                    uint32_t al[4] = {rl[0], rl[2], rl[1], rl[3]};
                    mma16816(acc[mt], ah, bph[ks]);
                    mma16816(acc[mt], al, bph[ks]);
                    mma16816(acc[mt], ah, bpl[ks]);
                }
            }
        }
        __syncthreads();
    }

    // ---- epilogue: divide by Z, stage to SMEM for coalesced write ----
    float rz0 = 1.f / stz[2 * tig];
    float rz1 = 1.f / stz[2 * tig + 1];
    float* fxw = (float*)(fsm + F_XHI);      // reuse as [8][520]
#pragma unroll
    for (int mt = 0; mt < 4; mt++) {
        int col = w * 64 + mt * 16;
        fxw[(2 * tig) * 520 + col + gid]         = acc[mt][0] * rz0;
        fxw[(2 * tig + 1) * 520 + col + gid]     = acc[mt][1] * rz1;
        fxw[(2 * tig) * 520 + col + 8 + gid]     = acc[mt][2] * rz0;
        fxw[(2 * tig + 1) * 520 + col + 8 + gid] = acc[mt][3] * rz1;
    }
    __syncthreads();
#pragma unroll
    for (int i = 0; i < 16; i++) {
        int idx = t + 256 * i;                    // over [8][512]
        int h = idx >> 9, col = idx & 511;
        g_xw[((size_t)b * Hh + h) * Ee + col] = fxw[h * 520 + col];
    }
}

// ---------------- LayerNorm over rows of outbuf -> d_out -----------------
__global__ void __launch_bounds__(256) ln_kernel(const float* __restrict__ lng,
                                                 const float* __restrict__ lnb,
                                                 float* __restrict__ out)
{
    int b = blockIdx.x;
    int t = threadIdx.x;
    float v0 = g_outbuf[(long)b * Ee + t];
    float v1 = g_outbuf[(long)b * Ee + t + 256];
    float s = v0 + v1;
    float q = v0 * v0 + v1 * v1;
#pragma unroll
    for (int o = 16; o; o >>= 1) {
        s += __shfl_xor_sync(0xffffffffu, s, o);
        q += __shfl_xor_sync(0xffffffffu, q, o);
    }
    __shared__ float ss[8], qs[8];
    __shared__ float mu_s, r_s;
    int wid = t >> 5, lane = t & 31;
    if (lane == 0) { ss[wid] = s; qs[wid] = q; }
    __syncthreads();
    if (t == 0) {
        float S = 0.f, Q = 0.f;
#pragma unroll
        for (int i = 0; i < 8; i++) { S += ss[i]; Q += qs[i]; }
        float mu = S / (float)Ee;
        float var = Q / (float)Ee - mu * mu;
        mu_s = mu;
        r_s = 1.f / sqrtf(var + 1e-5f);
    }
    __syncthreads();
    float mu = mu_s, r = r_s;
    out[(long)b * Ee + t]       = (v0 - mu) * r * lng[t]       + lnb[t];
    out[(long)b * Ee + t + 256] = (v1 - mu) * r * lng[t + 256] + lnb[t + 256];
}

// ---------------- launch -----------------
extern "C" void kernel_launch(void* const* d_in, const int* in_sizes, int n_in,
                              void* d_out, int out_size)
{
    (void)in_sizes; (void)n_in; (void)out_size;
    const float* X        = (const float*)d_in[0];
    const float* scaffold = (const float*)d_in[1];
    const float* Wq       = (const float*)d_in[2];
    const float* bq       = (const float*)d_in[3];
    const float* Wk       = (const float*)d_in[4];
    const float* Wv       = (const float*)d_in[6];
    const float* bv       = (const float*)d_in[7];
    const float* ipw      = (const float*)d_in[8];
    const float* ipb      = (const float*)d_in[9];
    const float* mow      = (const float*)d_in[10];
    const float* mob      = (const float*)d_in[11];
    const float* ow       = (const float*)d_in[12];
    const float* ob       = (const float*)d_in[13];
    const float* lng      = (const float*)d_in[14];
    const float* lnb      = (const float*)d_in[15];
    const int*   batch    = (const int*)d_in[16];

    void* p;
    cudaGetSymbolAddress(&p, g_Acat);   float* Acat   = (float*)p;
    cudaGetSymbolAddress(&p, g_Bcat);   float* Bcat   = (float*)p;
    cudaGetSymbolAddress(&p, g_Weff);   float* Weff   = (float*)p;
    cudaGetSymbolAddress(&p, g_beff);   float* beff   = (float*)p;
    cudaGetSymbolAddress(&p, g_qq);     float* qq     = (float*)p;
    cudaGetSymbolAddress(&p, g_qhat);   float* qhat   = (float*)p;
    cudaGetSymbolAddress(&p, g_xw);     float* xw     = (float*)p;
    cudaGetSymbolAddress(&p, g_pooled); float* pooled = (float*)p;
    cudaGetSymbolAddress(&p, g_outbuf); float* outbuf = (float*)p;

    cudaFuncSetAttribute(tcgemm<false, false>,
                         cudaFuncAttributeMaxDynamicSharedMemorySize, SM_TOTAL);
    cudaFuncSetAttribute(tcgemm<true, true>,
                         cudaFuncAttributeMaxDynamicSharedMemorySize, SM_TOTAL);
    cudaFuncSetAttribute(qhat_gemm,
                         cudaFuncAttributeMaxDynamicSharedMemorySize, SM_TOTAL);
    cudaFuncSetAttribute(fused_attn_kernel,
                         cudaFuncAttributeMaxDynamicSharedMemorySize, SMEM_FA);

    cudaMemcpyAsync(Acat,          ipw, (size_t)3 * EE * sizeof(float), cudaMemcpyDeviceToDevice, 0);
    cudaMemcpyAsync(Acat + 3 * EE, ow,  (size_t)EE * sizeof(float),     cudaMemcpyDeviceToDevice, 0);
    cudaMemcpyAsync(Bcat,          Wq,  (size_t)EE * sizeof(float),     cudaMemcpyDeviceToDevice, 0);
    cudaMemcpyAsync(Bcat + EE,     Wk,  (size_t)EE * sizeof(float),     cudaMemcpyDeviceToDevice, 0);
    cudaMemcpyAsync(Bcat + 2 * EE, Wv,  (size_t)EE * sizeof(float),     cudaMemcpyDeviceToDevice, 0);
    cudaMemcpyAsync(Bcat + 3 * EE, mow, (size_t)EE * sizeof(float),     cudaMemcpyDeviceToDevice, 0);

    tcgemm<false, false><<<dim3(8, 4, 4), 256, SM_TOTAL>>>(Acat, Bcat, Weff, nullptr,
        512, 512, 512, 512, (long)EE, (long)EE, (long)EE, 0, 1.f);

    bias_fold<<<192, 256>>>(ipw, ipb, bq, bv, ow, mob, ob);

    tcgemm<true, true><<<dim3(8, 32, 1), 256, SM_TOTAL>>>(scaffold, Weff, qq, beff,
        512, Ee, Ee, Ee, 0, 0, 0, 0, 1.f);

    qhat_gemm<<<dim3(1, 32, 8), 256, SM_TOTAL>>>(qq, Weff + EE, qhat);

    segstart_kernel<<<Nn / 256, 256>>>(batch);

    fused_attn_kernel<<<Bb, 256, SMEM_FA>>>(X);

    tcgemm<true, true><<<dim3(1, 32, 8), 256, SM_TOTAL>>>(xw, Weff + 2 * EE, pooled, beff + Ee,
        512, Hh * Ee, Ee, Ee, (long)Ee, (long)Dd * Ee, (long)Dd, Dd, 1.f);

    tcgemm<true, true><<<dim3(8, 32, 1), 256, SM_TOTAL>>>(pooled, Weff + 3 * EE, outbuf, beff + 2 * Ee,
        512, Ee, Ee, Ee, 0, 0, 0, 0, 1.f);

    ln_kernel<<<Bb, 256>>>(lng, lnb, (float*)d_out);
}

// round 9
// speedup vs baseline: 1.2777x; 1.0318x over previous
#include <cuda_runtime.h>
#include <cuda_bf16.h>
#include <math.h>
#include <stdint.h>

#define Nn 131072
#define Bb 4096
#define Ee 512
#define Hh 8
#define Dd 64
#define EE (Ee*Ee)

// ---------------- scratch (device globals; no allocation allowed) ----------------
__device__ __align__(16) __nv_bfloat16 g_AcatH[4*EE], g_AcatL[4*EE];
__device__ __align__(16) __nv_bfloat16 g_BcatH[4*EE], g_BcatL[4*EE];
__device__ __align__(16) __nv_bfloat16 g_scafH[Bb*Ee], g_scafL[Bb*Ee];
__device__ __align__(16) __nv_bfloat16 g_WeffH[4*EE], g_WeffL[4*EE];
__device__ __align__(16) __nv_bfloat16 g_qqH[Bb*Ee], g_qqL[Bb*Ee];
__device__ __align__(16) __nv_bfloat16 g_xwH[(size_t)Bb*Hh*Ee], g_xwL[(size_t)Bb*Hh*Ee];
__device__ __align__(16) __nv_bfloat16 g_pooledH[Bb*Ee], g_pooledL[Bb*Ee];
__device__ __align__(16) float g_beff[3*Ee];
__device__ __align__(16) float g_qhat[(size_t)Bb*Hh*Ee];
__device__ int   g_segstart[Bb+1];
__device__ __align__(16) float g_outbuf[Bb*Ee];

// ================= helpers =================
__device__ __forceinline__ uint32_t smem_u32(const void* p) {
    uint32_t a;
    asm("{ .reg .u64 t; cvta.to.shared.u64 t, %1; cvt.u32.u64 %0, t; }" : "=r"(a) : "l"(p));
    return a;
}
__device__ __forceinline__ void ldsm4(uint32_t* r, uint32_t addr) {
    asm volatile("ldmatrix.sync.aligned.m8n8.x4.shared.b16 {%0,%1,%2,%3}, [%4];"
        : "=r"(r[0]), "=r"(r[1]), "=r"(r[2]), "=r"(r[3]) : "r"(addr));
}
__device__ __forceinline__ void ldsm4t(uint32_t* r, uint32_t addr) {
    asm volatile("ldmatrix.sync.aligned.m8n8.x4.trans.shared.b16 {%0,%1,%2,%3}, [%4];"
        : "=r"(r[0]), "=r"(r[1]), "=r"(r[2]), "=r"(r[3]) : "r"(addr));
}
__device__ __forceinline__ void mma16816(float* c, const uint32_t* a, const uint32_t* b) {
    asm volatile("mma.sync.aligned.m16n8k16.row.col.f32.bf16.bf16.f32 "
        "{%0,%1,%2,%3}, {%4,%5,%6,%7}, {%8,%9}, {%0,%1,%2,%3};"
        : "+f"(c[0]), "+f"(c[1]), "+f"(c[2]), "+f"(c[3])
        : "r"(a[0]), "r"(a[1]), "r"(a[2]), "r"(a[3]), "r"(b[0]), "r"(b[1]));
}
__device__ __forceinline__ void split4(float4 v, uint2& hi, uint2& lo) {
    __nv_bfloat162 h0 = __floats2bfloat162_rn(v.x, v.y);
    __nv_bfloat162 h1 = __floats2bfloat162_rn(v.z, v.w);
    float2 f0 = __bfloat1622float2(h0);
    float2 f1 = __bfloat1622float2(h1);
    __nv_bfloat162 l0 = __floats2bfloat162_rn(v.x - f0.x, v.y - f0.y);
    __nv_bfloat162 l1 = __floats2bfloat162_rn(v.z - f1.x, v.w - f1.y);
    hi.x = *(uint32_t*)&h0; hi.y = *(uint32_t*)&h1;
    lo.x = *(uint32_t*)&l0; lo.y = *(uint32_t*)&l1;
}
__device__ __forceinline__ void store_split2(__nv_bfloat16* H, __nv_bfloat16* L,
                                             size_t off, float2 v) {
    __nv_bfloat162 h = __floats2bfloat162_rn(v.x, v.y);
    float2 hf = __bfloat1622float2(h);
    __nv_bfloat162 l = __floats2bfloat162_rn(v.x - hf.x, v.y - hf.y);
    *(uint32_t*)&H[off] = *(uint32_t*)&h;
    *(uint32_t*)&L[off] = *(uint32_t*)&l;
}

#define CPA16(dst, src) \
    asm volatile("cp.async.cg.shared.global [%0], [%1], 16;" :: "r"(dst), "l"(src))
#define CPA_COMMIT() asm volatile("cp.async.commit_group;" ::: "memory")
#define CPA_WAIT1()  asm volatile("cp.async.wait_group 1;" ::: "memory")
#define CPA_WAIT0()  asm volatile("cp.async.wait_group 0;" ::: "memory")

// ================= split kernels =================
// weights concat: z 0-2: ipw thirds -> Acat; z=3: ow -> Acat+3EE;
// z 4-7: Wq,Wk,Wv,mow -> Bcat
__global__ void __launch_bounds__(256) split_cat(
    const float* __restrict__ ipw, const float* __restrict__ ow,
    const float* __restrict__ wq,  const float* __restrict__ wk,
    const float* __restrict__ wv,  const float* __restrict__ mow)
{
    int z = blockIdx.z;
    int id = blockIdx.x * 256 + threadIdx.x;      // float4 index within EE/4
    const float* src;
    __nv_bfloat16 *dh, *dl;
    size_t off;
    if (z < 3)       { src = ipw + (size_t)z * EE; dh = g_AcatH; dl = g_AcatL; off = (size_t)z * EE; }
    else if (z == 3) { src = ow;                   dh = g_AcatH; dl = g_AcatL; off = (size_t)3 * EE; }
    else {
        const float* s4[4] = {wq, wk, wv, mow};
        src = s4[z - 4]; dh = g_BcatH; dl = g_BcatL; off = (size_t)(z - 4) * EE;
    }
    float4 v = ((const float4*)src)[id];
    uint2 hi, lo;
    split4(v, hi, lo);
    *(uint2*)&dh[off + (size_t)id * 4] = hi;
    *(uint2*)&dl[off + (size_t)id * 4] = lo;
}

__global__ void __launch_bounds__(256) split_one(const float* __restrict__ src,
                                                 __nv_bfloat16* dh, __nv_bfloat16* dl)
{
    int id = blockIdx.x * 256 + threadIdx.x;
    float4 v = ((const float4*)src)[id];
    uint2 hi, lo;
    split4(v, hi, lo);
    *(uint2*)&dh[(size_t)id * 4] = hi;
    *(uint2*)&dl[(size_t)id * 4] = lo;
}

// ================= pipelined HMMA GEMM on pre-split bf16 hi/lo =================
// C = alpha * A @ op(B) (+ bias). BM=128, BN=64, BK=64. 2-stage cp.async pipeline.
// SMEM rows padded to 144B (R3-proven conflict-free ldmatrix).
#define ROWB 144
#define S_AHI 0
#define S_ALO 18432
#define S_BHI 36864
#define S_BLO 46080
#define STAGE 55296
#define SM2_TOTAL (2*STAGE)

template<bool TRANSB, bool HASBIAS, bool CSPLIT>
__global__ void __launch_bounds__(256, 2)
tcgemm2(const __nv_bfloat16* __restrict__ Ahi, const __nv_bfloat16* __restrict__ Alo,
        const __nv_bfloat16* __restrict__ Bhi, const __nv_bfloat16* __restrict__ Blo,
        float* __restrict__ Cf, __nv_bfloat16* __restrict__ Chi, __nv_bfloat16* __restrict__ Clo,
        const float* __restrict__ bias,
        int K, int lda, int ldb, int ldc,
        long zA, long zB, long zC, int zBias, float alpha)
{
    extern __shared__ __align__(16) char sm[];
    uint32_t sb = smem_u32(sm);

    int z = blockIdx.z;
    Ahi += (size_t)z * zA;  Alo += (size_t)z * zA;
    Bhi += (size_t)z * zB;  Blo += (size_t)z * zB;
    int bm = blockIdx.y * 128;
    int bn = blockIdx.x * 64;
    int tid = threadIdx.x;
    int wid = tid >> 5;
    int lane = tid & 31;
    int wm = wid & 3;
    int wn = wid >> 2;

    // cp.async per-thread source bases
    int trow = tid >> 3, tkc = tid & 7;
    const __nv_bfloat16* pAh = Ahi + (size_t)(bm + trow) * lda + tkc * 8;
    const __nv_bfloat16* pAl = Alo + (size_t)(bm + trow) * lda + tkc * 8;
    const __nv_bfloat16* pBh;
    const __nv_bfloat16* pBl;
    if (TRANSB) {
        pBh = Bhi + (size_t)(bn + trow) * ldb + tkc * 8;
        pBl = Blo + (size_t)(bn + trow) * ldb + tkc * 8;
    } else {
        pBh = Bhi + (size_t)trow * ldb + bn + tkc * 8;
        pBl = Blo + (size_t)trow * ldb + bn + tkc * 8;
    }
    uint32_t dA = sb + (uint32_t)trow * ROWB + tkc * 16;
    uint32_t dB = sb + S_BHI + (uint32_t)trow * ROWB + tkc * 16;

#define G2_ISSUE(k0, st) do { \
    _Pragma("unroll") \
    for (int i = 0; i < 4; i++) { \
        CPA16(dA + (st) + i * 4608,         pAh + (k0) + (size_t)i * 32 * lda); \
        CPA16(dA + (st) + S_ALO + i * 4608, pAl + (k0) + (size_t)i * 32 * lda); \
    } \
    _Pragma("unroll") \
    for (int i = 0; i < 2; i++) { \
        if (TRANSB) { \
            CPA16(dB + (st) + i * 4608,                   pBh + (k0) + (size_t)i * 32 * ldb); \
            CPA16(dB + (st) + (S_BLO-S_BHI) + i * 4608,   pBl + (k0) + (size_t)i * 32 * ldb); \
        } else { \
            CPA16(dB + (st) + i * 4608,                   pBh + (size_t)((k0) + i * 32) * ldb); \
            CPA16(dB + (st) + (S_BLO-S_BHI) + i * 4608,   pBl + (size_t)((k0) + i * 32) * ldb); \
        } \
    } \
    CPA_COMMIT(); \
} while (0)

    float acc[2][4][4];
#pragma unroll
    for (int i = 0; i < 2; i++)
#pragma unroll
        for (int f = 0; f < 4; f++)
#pragma unroll
            for (int r = 0; r < 4; r++) acc[i][f][r] = 0.f;

    int am = ((lane >> 3) & 1) * 8 + (lane & 7);
    int ak = (lane >> 4) * 8;
    int bnr = ((lane >> 4) & 1) * 8 + (lane & 7);
    int bkc = ((lane >> 3) & 1) * 8;
    int bkr = ((lane >> 3) & 1) * 8 + (lane & 7);
    int bnc = (lane >> 4) * 8;

    const int nch = K / 64;
    G2_ISSUE(0, 0);

    for (int ch = 0; ch < nch; ch++) {
        bool more = (ch + 1 < nch);
        if (more) G2_ISSUE((ch + 1) * 64, ((ch + 1) & 1) * STAGE);
        if (more) CPA_WAIT1(); else CPA_WAIT0();
        __syncthreads();

        uint32_t cur = (uint32_t)(ch & 1) * STAGE;
#pragma unroll
        for (int ks = 0; ks < 4; ks++) {
            int kk = ks * 16;
            uint32_t bh[4][2], bl[4][2];
#pragma unroll
            for (int g = 0; g < 2; g++) {
                uint32_t r[4];
                if (TRANSB) {
                    uint32_t off = cur + S_BHI + (uint32_t)(wn * 32 + g * 16 + bnr) * ROWB + (kk + bkc) * 2;
                    ldsm4(r, sb + off);
                    bh[g*2][0]=r[0]; bh[g*2][1]=r[1]; bh[g*2+1][0]=r[2]; bh[g*2+1][1]=r[3];
                    ldsm4(r, sb + off + (S_BLO - S_BHI));
                    bl[g*2][0]=r[0]; bl[g*2][1]=r[1]; bl[g*2+1][0]=r[2]; bl[g*2+1][1]=r[3];
                } else {
                    uint32_t off = cur + S_BHI + (uint32_t)(kk + bkr) * ROWB + (wn * 32 + g * 16 + bnc) * 2;
                    ldsm4t(r, sb + off);
                    bh[g*2][0]=r[0]; bh[g*2][1]=r[1]; bh[g*2+1][0]=r[2]; bh[g*2+1][1]=r[3];
                    ldsm4t(r, sb + off + (S_BLO - S_BHI));
                    bl[g*2][0]=r[0]; bl[g*2][1]=r[1]; bl[g*2+1][0]=r[2]; bl[g*2+1][1]=r[3];
                }
            }
            uint32_t ah[2][4], al[2][4];
#pragma unroll
            for (int i = 0; i < 2; i++) {
                uint32_t off = cur + (uint32_t)(wm * 32 + i * 16 + am) * ROWB + (kk + ak) * 2;
                ldsm4(ah[i], sb + off);
                ldsm4(al[i], sb + off + S_ALO);
            }
#pragma unroll
            for (int i = 0; i < 2; i++)
#pragma unroll
                for (int f = 0; f < 4; f++) {
                    mma16816(acc[i][f], ah[i], bh[f]);
                    mma16816(acc[i][f], ah[i], bl[f]);
                    mma16816(acc[i][f], al[i], bh[f]);
                }
        }
        __syncthreads();
    }

#pragma unroll
    for (int i = 0; i < 2; i++) {
#pragma unroll
        for (int f = 0; f < 4; f++) {
            int row = bm + wm * 32 + i * 16 + (lane >> 2);
            int col = bn + wn * 32 + f * 8 + (lane & 3) * 2;
            float2 bb = make_float2(0.f, 0.f);
            if (HASBIAS) bb = *(const float2*)&bias[(long)z * zBias + col];
            float2 v0, v1;
            v0.x = alpha * acc[i][f][0] + bb.x;
            v0.y = alpha * acc[i][f][1] + bb.y;
            v1.x = alpha * acc[i][f][2] + bb.x;
            v1.y = alpha * acc[i][f][3] + bb.y;
            size_t o0 = (size_t)z * zC + (size_t)row * ldc + col;
            size_t o1 = (size_t)z * zC + (size_t)(row + 8) * ldc + col;
            if (CSPLIT) {
                store_split2(Chi, Clo, o0, v0);
                store_split2(Chi, Clo, o1, v1);
            } else {
                *(float2*)&Cf[o0] = v0;
                *(float2*)&Cf[o1] = v1;
            }
        }
    }
#undef G2_ISSUE
}

// ================= qhat GEMM: A-resident, cp.async double-buffered B ==========
// Per head z: qhat[:, z*512+:] = 0.125 * qq[:, z*64:(z+1)*64] @ Wk_eff_z [64,512]
#define Q_AHI 0
#define Q_ALO 18432
#define Q_B0  36864
#define Q_BSZ 18432
#define QH_TOTAL (Q_B0 + 2*Q_BSZ)

__global__ void __launch_bounds__(256, 2)
qhat2(const __nv_bfloat16* __restrict__ Ahi, const __nv_bfloat16* __restrict__ Alo,
      const __nv_bfloat16* __restrict__ WkH, const __nv_bfloat16* __restrict__ WkL,
      float* __restrict__ qhat)
{
    extern __shared__ __align__(16) char sm[];
    uint32_t sb = smem_u32(sm);

    int z = blockIdx.z;
    int bm = blockIdx.y * 128;
    const __nv_bfloat16* BH = WkH + (size_t)z * Dd * Ee;   // [64][512]
    const __nv_bfloat16* BL = WkL + (size_t)z * Dd * Ee;
    float* C = qhat + (size_t)z * Ee;

    int tid = threadIdx.x;
    int lane = tid & 31;
    int wid = tid >> 5;
    int wm = wid & 3;
    int wn = wid >> 2;

    int trow = tid >> 3, tkc = tid & 7;
    // A: qq rows, k-slice z*64
    {
        const __nv_bfloat16* pAh = Ahi + (size_t)(bm + trow) * Ee + z * Dd + tkc * 8;
        const __nv_bfloat16* pAl = Alo + (size_t)(bm + trow) * Ee + z * Dd + tkc * 8;
        uint32_t dA = sb + (uint32_t)trow * ROWB + tkc * 16;
#pragma unroll
        for (int i = 0; i < 4; i++) {
            CPA16(dA + i * 4608,         pAh + (size_t)i * 32 * Ee);
            CPA16(dA + Q_ALO + i * 4608, pAl + (size_t)i * 32 * Ee);
        }
    }
    // B tile issue: rows k (64), cols nt*64..+64
    const __nv_bfloat16* pBh = BH + (size_t)trow * Ee + tkc * 8;
    const __nv_bfloat16* pBl = BL + (size_t)trow * Ee + tkc * 8;
    uint32_t dB = sb + Q_B0 + (uint32_t)trow * ROWB + tkc * 16;

#define QB_ISSUE(nt, s) do { \
    _Pragma("unroll") \
    for (int i = 0; i < 2; i++) { \
        CPA16(dB + (s) * Q_BSZ + i * 4608,        pBh + (nt) * 64 + (size_t)i * 32 * Ee); \
        CPA16(dB + (s) * Q_BSZ + 9216 + i * 4608, pBl + (nt) * 64 + (size_t)i * 32 * Ee); \
    } \
    CPA_COMMIT(); \
} while (0)

    QB_ISSUE(0, 0);          // group0 = A + B0
    int am = ((lane >> 3) & 1) * 8 + (lane & 7);
    int ak = (lane >> 4) * 8;
    int bkr = ((lane >> 3) & 1) * 8 + (lane & 7);
    int bnc = (lane >> 4) * 8;

    for (int nt = 0; nt < 8; nt++) {
        bool more = (nt + 1 < 8);
        if (more) QB_ISSUE(nt + 1, (nt + 1) & 1);
        if (more) CPA_WAIT1(); else CPA_WAIT0();
        __syncthreads();

        uint32_t bcur = Q_B0 + (uint32_t)(nt & 1) * Q_BSZ;
        float acc[2][4][4];
#pragma unroll
        for (int i = 0; i < 2; i++)
#pragma unroll
            for (int f = 0; f < 4; f++)
#pragma unroll
                for (int r = 0; r < 4; r++) acc[i][f][r] = 0.f;

#pragma unroll
        for (int ks = 0; ks < 4; ks++) {
            int kk = ks * 16;
            uint32_t bh[4][2], bl[4][2];
#pragma unroll
            for (int g = 0; g < 2; g++) {
                uint32_t r[4];
                uint32_t off = bcur + (uint32_t)(kk + bkr) * ROWB + (wn * 32 + g * 16 + bnc) * 2;
                ldsm4t(r, sb + off);
                bh[g*2][0]=r[0]; bh[g*2][1]=r[1]; bh[g*2+1][0]=r[2]; bh[g*2+1][1]=r[3];
                ldsm4t(r, sb + off + 9216);
                bl[g*2][0]=r[0]; bl[g*2][1]=r[1]; bl[g*2+1][0]=r[2]; bl[g*2+1][1]=r[3];
            }
            uint32_t ah[2][4], al[2][4];
#pragma unroll
            for (int i = 0; i < 2; i++) {
                uint32_t off = (uint32_t)(wm * 32 + i * 16 + am) * ROWB + (kk + ak) * 2;
                ldsm4(ah[i], sb + off);
                ldsm4(al[i], sb + off + Q_ALO);
            }
#pragma unroll
            for (int i = 0; i < 2; i++)
#pragma unroll
                for (int f = 0; f < 4; f++) {
                    mma16816(acc[i][f], ah[i], bh[f]);
                    mma16816(acc[i][f], ah[i], bl[f]);
                    mma16816(acc[i][f], al[i], bh[f]);
                }
        }

#pragma unroll
        for (int i = 0; i < 2; i++) {
#pragma unroll
            for (int f = 0; f < 4; f++) {
                int row = bm + wm * 32 + i * 16 + (lane >> 2);
                int col = nt * 64 + wn * 32 + f * 8 + (lane & 3) * 2;
                float2 o0, o1;
                o0.x = 0.125f * acc[i][f][0];
                o0.y = 0.125f * acc[i][f][1];
                o1.x = 0.125f * acc[i][f][2];
                o1.y = 0.125f * acc[i][f][3];
                *(float2*)&C[(size_t)row * (Hh * Ee) + col] = o0;
                *(float2*)&C[(size_t)(row + 8) * (Hh * Ee) + col] = o1;
            }
        }
        __syncthreads();
    }
#undef QB_ISSUE
}

// ---------------- bias folding ----------------
__global__ void bias_fold(const float* __restrict__ ipw, const float* __restrict__ ipb,
                          const float* __restrict__ bq,  const float* __restrict__ bv,
                          const float* __restrict__ out_w, const float* __restrict__ mob,
                          const float* __restrict__ out_b)
{
    int gw = (blockIdx.x * blockDim.x + threadIdx.x) >> 5;
    int lane = threadIdx.x & 31;
    if (gw >= 3 * Ee) return;
    int which = gw / Ee, i = gw % Ee;
    const float* rowp;
    const float* vec;
    float add;
    if (which == 0)      { rowp = ipw + (long)i * Ee;            vec = bq;  add = ipb[i]; }
    else if (which == 1) { rowp = ipw + (long)(2 * Ee + i) * Ee; vec = bv;  add = ipb[2 * Ee + i]; }
    else                 { rowp = out_w + (long)i * Ee;          vec = mob; add = out_b[i]; }
    float s = 0.f;
    for (int k = lane; k < Ee; k += 32) s += rowp[k] * vec[k];
#pragma unroll
    for (int o = 16; o; o >>= 1) s += __shfl_xor_sync(0xffffffffu, s, o);
    if (lane == 0) g_beff[gw] = s + add;
}

// ---------------- segment starts ----------------
__global__ void segstart_kernel(const int* __restrict__ batch)
{
    int n = blockIdx.x * 256 + threadIdx.x;
    if (n < Nn) {
        int b = batch[n];
        if (n == 0 || batch[n - 1] != b) g_segstart[b] = n;
    }
    if (n == 0) g_segstart[Bb] = Nn;
}

// ================= fused segment attention, HMMA (R8-proven; epilogue -> hi/lo) ==
#define XROW   1040
#define F_XHI  0
#define F_XLO  33280
#define F_QHI  66560
#define F_QLO  74880
#define F_LGP  83200
#define F_LGS  91392
#define F_PHI  92544
#define F_PLO  93056
#define F_STM  93568
#define F_STZ  93600
#define F_STF  93632
#define SMEM_FA 93664

__global__ void __launch_bounds__(256)
fused_attn_kernel(const float* __restrict__ X)
{
    extern __shared__ __align__(16) char fsm[];
    uint32_t sb = smem_u32(fsm);

    int b = blockIdx.x;
    int t = threadIdx.x;
    int w = t >> 5, lane = t & 31;
    int gid = lane >> 2, tig = lane & 3;
    int s0 = g_segstart[b], e0 = g_segstart[b + 1];

    float* stm = (float*)(fsm + F_STM);
    float* stz = (float*)(fsm + F_STZ);
    float* stf = (float*)(fsm + F_STF);
    float* lgs = (float*)(fsm + F_LGS);
    float* lgp = (float*)(fsm + F_LGP);

#pragma unroll
    for (int i = 0; i < 4; i++) {
        int flat = t + 256 * i;
        int c4 = flat & 127;
        float4 v = *(const float4*)&g_qhat[(size_t)b * (Hh * Ee) + (size_t)flat * 4];
        uint2 hi, lo;
        split4(v, hi, lo);
        uint32_t off = (uint32_t)(flat >> 7) * XROW + (uint32_t)c4 * 8;
        *(uint2*)(fsm + F_QHI + off) = hi;
        *(uint2*)(fsm + F_QLO + off) = lo;
    }
    if (t < 8) { stm[t] = -1e30f; stz[t] = 0.f; }
    __syncthreads();

    int am  = ((lane >> 3) & 1) * 8 + (lane & 7);
    int ak  = (lane >> 4) * 8;
    int bkr = ((lane >> 3) & 1) * 8 + (lane & 7);
    int bnc = (lane >> 4) * 8;
    int qrow = lane & 7;
    int qc8  = (lane >> 3) * 8;

    float acc[4][4];
#pragma unroll
    for (int mt = 0; mt < 4; mt++)
#pragma unroll
        for (int r = 0; r < 4; r++) acc[mt][r] = 0.f;

    for (int base = s0; base < e0; base += 32) {
        int cnt = min(32, e0 - base);

#pragma unroll
        for (int i = 0; i < 16; i++) {
            int flat = t + 256 * i;
            int node = flat >> 7, c4 = flat & 127;
            float4 v = make_float4(0.f, 0.f, 0.f, 0.f);
            if (node < cnt)
                v = *(const float4*)&X[(size_t)(base + node) * Ee + c4 * 4];
            uint2 hi, lo;
            split4(v, hi, lo);
            uint32_t off = (uint32_t)node * XROW + (uint32_t)c4 * 8;
            *(uint2*)(fsm + F_XHI + off) = hi;
            *(uint2*)(fsm + F_XLO + off) = lo;
        }
        __syncthreads();

        {
            float lg[2][4];
#pragma unroll
            for (int m = 0; m < 2; m++)
#pragma unroll
                for (int r = 0; r < 4; r++) lg[m][r] = 0.f;

            int ks0 = w * 64;
#pragma unroll
            for (int kb = 0; kb < 2; kb++) {
                int kbase = ks0 + kb * 32;
                uint32_t rq[4];
                uint32_t qoff = (uint32_t)qrow * XROW + (uint32_t)(kbase + qc8) * 2;
                uint32_t bqh[2][2], bql[2][2];
                ldsm4(rq, sb + F_QHI + qoff);
                bqh[0][0]=rq[0]; bqh[0][1]=rq[1]; bqh[1][0]=rq[2]; bqh[1][1]=rq[3];
                ldsm4(rq, sb + F_QLO + qoff);
                bql[0][0]=rq[0]; bql[0][1]=rq[1]; bql[1][0]=rq[2]; bql[1][1]=rq[3];
#pragma unroll
                for (int ks = 0; ks < 2; ks++) {
                    int kk = kbase + ks * 16;
                    uint32_t ah[2][4], al[2][4];
#pragma unroll
                    for (int m = 0; m < 2; m++) {
                        uint32_t aoff = (uint32_t)(m * 16 + am) * XROW + (uint32_t)(kk + ak) * 2;
                        ldsm4(ah[m], sb + F_XHI + aoff);
                        ldsm4(al[m], sb + F_XLO + aoff);
                    }
#pragma unroll
                    for (int m = 0; m < 2; m++) {
                        mma16816(lg[m], ah[m], bqh[ks]);
                        mma16816(lg[m], ah[m], bql[ks]);
                        mma16816(lg[m], al[m], bqh[ks]);
                    }
                }
            }
            float* lp = lgp + w * 256;
#pragma unroll
            for (int m = 0; m < 2; m++) {
                lp[(m * 16 + gid) * 8 + 2 * tig]     = lg[m][0];
                lp[(m * 16 + gid) * 8 + 2 * tig + 1] = lg[m][1];
                lp[(m * 16 + gid + 8) * 8 + 2 * tig]     = lg[m][2];
                lp[(m * 16 + gid + 8) * 8 + 2 * tig + 1] = lg[m][3];
            }
        }
        __syncthreads();

        {
            float s = 0.f;
#pragma unroll
            for (int w2 = 0; w2 < 8; w2++) s += lgp[w2 * 256 + t];
            lgs[(t >> 3) * 9 + (t & 7)] = s;
        }
        __syncthreads();

        {
            float v = (lane < cnt) ? lgs[lane * 9 + w] : -1e30f;
            float mx = v;
#pragma unroll
            for (int o = 16; o; o >>= 1) mx = fmaxf(mx, __shfl_xor_sync(0xffffffffu, mx, o));
            float mo = stm[w];
            float mn = fmaxf(mo, mx);
            float p = (lane < cnt) ? __expf(v - mn) : 0.f;
            __nv_bfloat16 ph = __float2bfloat16(p);
            __nv_bfloat16 pl = __float2bfloat16(p - __bfloat162float(ph));
            ((__nv_bfloat16*)(fsm + F_PHI))[lane * 8 + w] = ph;
            ((__nv_bfloat16*)(fsm + F_PLO))[lane * 8 + w] = pl;
            float ssum = p;
#pragma unroll
            for (int o = 16; o; o >>= 1) ssum += __shfl_xor_sync(0xffffffffu, ssum, o);
            if (lane == 0) {
                float f = __expf(mo - mn);
                stf[w] = f;
                stm[w] = mn;
                stz[w] = stz[w] * f + ssum;
            }
        }
        __syncthreads();

        {
            float f0 = stf[2 * tig];
            float f1 = stf[2 * tig + 1];
#pragma unroll
            for (int mt = 0; mt < 4; mt++) {
                acc[mt][0] *= f0; acc[mt][1] *= f1;
                acc[mt][2] *= f0; acc[mt][3] *= f1;
            }
            uint32_t rp[4];
            uint32_t bph[2][2], bpl[2][2];
            ldsm4t(rp, sb + F_PHI + (uint32_t)lane * 16);
            bph[0][0]=rp[0]; bph[0][1]=rp[1]; bph[1][0]=rp[2]; bph[1][1]=rp[3];
            ldsm4t(rp, sb + F_PLO + (uint32_t)lane * 16);
            bpl[0][0]=rp[0]; bpl[0][1]=rp[1]; bpl[1][0]=rp[2]; bpl[1][1]=rp[3];

#pragma unroll
            for (int ks = 0; ks < 2; ks++) {
#pragma unroll
                for (int mt = 0; mt < 4; mt++) {
                    uint32_t aoff = (uint32_t)(ks * 16 + bkr) * XROW
                                  + (uint32_t)(w * 64 + mt * 16 + bnc) * 2;
                    uint32_t ra[4], rl[4];
                    ldsm4t(ra, sb + F_XHI + aoff);
                    ldsm4t(rl, sb + F_XLO + aoff);
                    uint32_t ah2[4] = {ra[0], ra[2], ra[1], ra[3]};
                    uint32_t al2[4] = {rl[0], rl[2], rl[1], rl[3]};
                    mma16816(acc[mt], ah2, bph[ks]);
                    mma16816(acc[mt], al2, bph[ks]);
                    mma16816(acc[mt], ah2, bpl[ks]);
                }
            }
        }
        __syncthreads();
    }

    // epilogue: divide by Z, stage to SMEM, write bf16 hi/lo
    float rz0 = 1.f / stz[2 * tig];
    float rz1 = 1.f / stz[2 * tig + 1];
    float* fxw = (float*)(fsm + F_XHI);      // reuse as [8][520]
#pragma unroll
    for (int mt = 0; mt < 4; mt++) {
        int col = w * 64 + mt * 16;
        fxw[(2 * tig) * 520 + col + gid]         = acc[mt][0] * rz0;
        fxw[(2 * tig + 1) * 520 + col + gid]     = acc[mt][1] * rz1;
        fxw[(2 * tig) * 520 + col + 8 + gid]     = acc[mt][2] * rz0;
        fxw[(2 * tig + 1) * 520 + col + 8 + gid] = acc[mt][3] * rz1;
    }
    __syncthreads();
#pragma unroll
    for (int i = 0; i < 8; i++) {
        int idx = t + 256 * i;                 // over [8][256] col-pairs
        int h = idx >> 8, cp = (idx & 255) * 2;
        float2 v = make_float2(fxw[h * 520 + cp], fxw[h * 520 + cp + 1]);
        store_split2(g_xwH, g_xwL, ((size_t)b * Hh + h) * Ee + cp, v);
    }
}

// ---------------- LayerNorm ----------------
__global__ void __launch_bounds__(256) ln_kernel(const float* __restrict__ lng,
                                                 const float* __restrict__ lnb,
                                                 float* __restrict__ out)
{
    int b = blockIdx.x;
    int t = threadIdx.x;
    float v0 = g_outbuf[(long)b * Ee + t];
    float v1 = g_outbuf[(long)b * Ee + t + 256];
    float s = v0 + v1;
    float q = v0 * v0 + v1 * v1;
#pragma unroll
    for (int o = 16; o; o >>= 1) {
        s += __shfl_xor_sync(0xffffffffu, s, o);
        q += __shfl_xor_sync(0xffffffffu, q, o);
    }
    __shared__ float ss[8], qs[8];
    __shared__ float mu_s, r_s;
    int wid = t >> 5, lane = t & 31;
    if (lane == 0) { ss[wid] = s; qs[wid] = q; }
    __syncthreads();
    if (t == 0) {
        float S = 0.f, Q = 0.f;
#pragma unroll
        for (int i = 0; i < 8; i++) { S += ss[i]; Q += qs[i]; }
        float mu = S / (float)Ee;
        float var = Q / (float)Ee - mu * mu;
        mu_s = mu;
        r_s = 1.f / sqrtf(var + 1e-5f);
    }
    __syncthreads();
    float mu = mu_s, r = r_s;
    out[(long)b * Ee + t]       = (v0 - mu) * r * lng[t]       + lnb[t];
    out[(long)b * Ee + t + 256] = (v1 - mu) * r * lng[t + 256] + lnb[t + 256];
}

// ---------------- launch ----------------
extern "C" void kernel_launch(void* const* d_in, const int* in_sizes, int n_in,
                              void* d_out, int out_size)
{
    (void)in_sizes; (void)n_in; (void)out_size;
    const float* X        = (const float*)d_in[0];
    const float* scaffold = (const float*)d_in[1];
    const float* Wq       = (const float*)d_in[2];
    const float* bq       = (const float*)d_in[3];
    const float* Wk       = (const float*)d_in[4];
    const float* Wv       = (const float*)d_in[6];
    const float* bv       = (const float*)d_in[7];
    const float* ipw      = (const float*)d_in[8];
    const float* ipb      = (const float*)d_in[9];
    const float* mow      = (const float*)d_in[10];
    const float* mob      = (const float*)d_in[11];
    const float* ow       = (const float*)d_in[12];
    const float* ob       = (const float*)d_in[13];
    const float* lng      = (const float*)d_in[14];
    const float* lnb      = (const float*)d_in[15];
    const int*   batch    = (const int*)d_in[16];

    void* p;
    cudaGetSymbolAddress(&p, g_AcatH);   __nv_bfloat16* AcatH = (__nv_bfloat16*)p;
    cudaGetSymbolAddress(&p, g_AcatL);   __nv_bfloat16* AcatL = (__nv_bfloat16*)p;
    cudaGetSymbolAddress(&p, g_BcatH);   __nv_bfloat16* BcatH = (__nv_bfloat16*)p;
    cudaGetSymbolAddress(&p, g_BcatL);   __nv_bfloat16* BcatL = (__nv_bfloat16*)p;
    cudaGetSymbolAddress(&p, g_scafH);   __nv_bfloat16* scafH = (__nv_bfloat16*)p;
    cudaGetSymbolAddress(&p, g_scafL);   __nv_bfloat16* scafL = (__nv_bfloat16*)p;
    cudaGetSymbolAddress(&p, g_WeffH);   __nv_bfloat16* WeffH = (__nv_bfloat16*)p;
    cudaGetSymbolAddress(&p, g_WeffL);   __nv_bfloat16* WeffL = (__nv_bfloat16*)p;
    cudaGetSymbolAddress(&p, g_qqH);     __nv_bfloat16* qqH   = (__nv_bfloat16*)p;
    cudaGetSymbolAddress(&p, g_qqL);     __nv_bfloat16* qqL   = (__nv_bfloat16*)p;
    cudaGetSymbolAddress(&p, g_xwH);     __nv_bfloat16* xwH   = (__nv_bfloat16*)p;
    cudaGetSymbolAddress(&p, g_xwL);     __nv_bfloat16* xwL   = (__nv_bfloat16*)p;
    cudaGetSymbolAddress(&p, g_pooledH); __nv_bfloat16* plH   = (__nv_bfloat16*)p;
    cudaGetSymbolAddress(&p, g_pooledL); __nv_bfloat16* plL   = (__nv_bfloat16*)p;
    cudaGetSymbolAddress(&p, g_beff);    float* beff  = (float*)p;
    cudaGetSymbolAddress(&p, g_qhat);    float* qhat  = (float*)p;
    cudaGetSymbolAddress(&p, g_outbuf);  float* outbuf = (float*)p;

    cudaFuncSetAttribute(tcgemm2<false, false, true>,
                         cudaFuncAttributeMaxDynamicSharedMemorySize, SM2_TOTAL);
    cudaFuncSetAttribute(tcgemm2<true, true, true>,
                         cudaFuncAttributeMaxDynamicSharedMemorySize, SM2_TOTAL);
    cudaFuncSetAttribute(tcgemm2<true, true, false>,
                         cudaFuncAttributeMaxDynamicSharedMemorySize, SM2_TOTAL);
    cudaFuncSetAttribute(qhat2,
                         cudaFuncAttributeMaxDynamicSharedMemorySize, QH_TOTAL);
    cudaFuncSetAttribute(fused_attn_kernel,
                         cudaFuncAttributeMaxDynamicSharedMemorySize, SMEM_FA);

    // pre-split weights + scaffold
    split_cat<<<dim3(256, 1, 8), 256>>>(ipw, ow, Wq, Wk, Wv, mow);
    split_one<<<Bb * Ee / 4 / 256, 256>>>(scaffold, scafH, scafL);

    // fold: Weff[z] = Acat[z] @ Bcat[z] (NN), write hi/lo
    tcgemm2<false, false, true><<<dim3(8, 4, 4), 256, SM2_TOTAL>>>(
        AcatH, AcatL, BcatH, BcatL, nullptr, WeffH, WeffL, nullptr,
        512, 512, 512, 512, (long)EE, (long)EE, (long)EE, 0, 1.f);

    bias_fold<<<192, 256>>>(ipw, ipb, bq, bv, ow, mob, ob);

    // qq = scaffold @ Wq_eff^T + bq_eff (NT), write hi/lo
    tcgemm2<true, true, true><<<dim3(8, 32, 1), 256, SM2_TOTAL>>>(
        scafH, scafL, WeffH, WeffL, nullptr, qqH, qqL, beff,
        512, Ee, Ee, Ee, 0, 0, 0, 0, 1.f);

    // qhat (A-resident, pipelined)
    qhat2<<<dim3(1, 32, 8), 256, QH_TOTAL>>>(qqH, qqL, WeffH + EE, WeffL + EE, qhat);

    segstart_kernel<<<Nn / 256, 256>>>(batch);

    fused_attn_kernel<<<Bb, 256, SMEM_FA>>>(X);

    // pooled[b, h*64+:] = xw[b,h,:] @ Wv_eff_h^T + bv_eff (NT), write hi/lo
    tcgemm2<true, true, true><<<dim3(1, 32, 8), 256, SM2_TOTAL>>>(
        xwH, xwL, WeffH + 2 * EE, WeffL + 2 * EE, nullptr, plH, plL, beff + Ee,
        512, Hh * Ee, Ee, Ee, (long)Ee, (long)Dd * Ee, (long)Dd, Dd, 1.f);

    // out = pooled @ Wo_eff^T + bo_eff (NT), write fp32
    tcgemm2<true, true, false><<<dim3(8, 32, 1), 256, SM2_TOTAL>>>(
        plH, plL, WeffH + 3 * EE, WeffL + 3 * EE, outbuf, nullptr, nullptr, beff + 2 * Ee,
        512, Ee, Ee, Ee, 0, 0, 0, 0, 1.f);

    ln_kernel<<<Bb, 256>>>(lng, lnb, (float*)d_out);
}

// round 10
// speedup vs baseline: 1.3313x; 1.0420x over previous
#include <cuda_runtime.h>
#include <cuda_bf16.h>
#include <math.h>
#include <stdint.h>

#define Nn 131072
#define Bb 4096
#define Ee 512
#define Hh 8
#define Dd 64
#define EE (Ee*Ee)

// ---------------- scratch (device globals; no allocation allowed) ----------------
__device__ __align__(16) __nv_bfloat16 g_AcatH[4*EE], g_AcatL[4*EE];
__device__ __align__(16) __nv_bfloat16 g_BcatH[4*EE], g_BcatL[4*EE];
__device__ __align__(16) __nv_bfloat16 g_scafH[Bb*Ee], g_scafL[Bb*Ee];
__device__ __align__(16) __nv_bfloat16 g_WeffH[4*EE], g_WeffL[4*EE];
__device__ __align__(16) __nv_bfloat16 g_qqH[Bb*Ee], g_qqL[Bb*Ee];
__device__ __align__(16) __nv_bfloat16 g_qhatH[(size_t)Bb*Hh*Ee], g_qhatL[(size_t)Bb*Hh*Ee];
__device__ __align__(16) __nv_bfloat16 g_xwH[(size_t)Bb*Hh*Ee], g_xwL[(size_t)Bb*Hh*Ee];
__device__ __align__(16) __nv_bfloat16 g_pooledH[Bb*Ee], g_pooledL[Bb*Ee];
__device__ __align__(16) float g_beff[3*Ee];
__device__ int   g_segstart[Bb+1];
__device__ __align__(16) float g_outbuf[Bb*Ee];

// ================= helpers =================
__device__ __forceinline__ uint32_t smem_u32(const void* p) {
    uint32_t a;
    asm("{ .reg .u64 t; cvta.to.shared.u64 t, %1; cvt.u32.u64 %0, t; }" : "=r"(a) : "l"(p));
    return a;
}
__device__ __forceinline__ void ldsm4(uint32_t* r, uint32_t addr) {
    asm volatile("ldmatrix.sync.aligned.m8n8.x4.shared.b16 {%0,%1,%2,%3}, [%4];"
        : "=r"(r[0]), "=r"(r[1]), "=r"(r[2]), "=r"(r[3]) : "r"(addr));
}
__device__ __forceinline__ void ldsm4t(uint32_t* r, uint32_t addr) {
    asm volatile("ldmatrix.sync.aligned.m8n8.x4.trans.shared.b16 {%0,%1,%2,%3}, [%4];"
        : "=r"(r[0]), "=r"(r[1]), "=r"(r[2]), "=r"(r[3]) : "r"(addr));
}
__device__ __forceinline__ void mma16816(float* c, const uint32_t* a, const uint32_t* b) {
    asm volatile("mma.sync.aligned.m16n8k16.row.col.f32.bf16.bf16.f32 "
        "{%0,%1,%2,%3}, {%4,%5,%6,%7}, {%8,%9}, {%0,%1,%2,%3};"
        : "+f"(c[0]), "+f"(c[1]), "+f"(c[2]), "+f"(c[3])
        : "r"(a[0]), "r"(a[1]), "r"(a[2]), "r"(a[3]), "r"(b[0]), "r"(b[1]));
}
__device__ __forceinline__ void split4(float4 v, uint2& hi, uint2& lo) {
    __nv_bfloat162 h0 = __floats2bfloat162_rn(v.x, v.y);
    __nv_bfloat162 h1 = __floats2bfloat162_rn(v.z, v.w);
    float2 f0 = __bfloat1622float2(h0);
    float2 f1 = __bfloat1622float2(h1);
    __nv_bfloat162 l0 = __floats2bfloat162_rn(v.x - f0.x, v.y - f0.y);
    __nv_bfloat162 l1 = __floats2bfloat162_rn(v.z - f1.x, v.w - f1.y);
    hi.x = *(uint32_t*)&h0; hi.y = *(uint32_t*)&h1;
    lo.x = *(uint32_t*)&l0; lo.y = *(uint32_t*)&l1;
}
__device__ __forceinline__ void store_split2(__nv_bfloat16* H, __nv_bfloat16* L,
                                             size_t off, float2 v) {
    __nv_bfloat162 h = __floats2bfloat162_rn(v.x, v.y);
    float2 hf = __bfloat1622float2(h);
    __nv_bfloat162 l = __floats2bfloat162_rn(v.x - hf.x, v.y - hf.y);
    *(uint32_t*)&H[off] = *(uint32_t*)&h;
    *(uint32_t*)&L[off] = *(uint32_t*)&l;
}

#define CPA16(dst, src) \
    asm volatile("cp.async.cg.shared.global [%0], [%1], 16;" :: "r"(dst), "l"(src))
#define CPA_COMMIT() asm volatile("cp.async.commit_group;" ::: "memory")
#define CPA_WAIT1()  asm volatile("cp.async.wait_group 1;" ::: "memory")
#define CPA_WAIT0()  asm volatile("cp.async.wait_group 0;" ::: "memory")

// ================= prep: all independent preprocessing in ONE launch ============
// blocks [0,2048): weight-concat split (z = blk>>8)
// blocks [2048,4096): scaffold split
// blocks [4096,4608): segment starts
// blocks [4608,4800): bias folding (vectorized, MLP 8)
__global__ void __launch_bounds__(256) prep(
    const float* __restrict__ ipw, const float* __restrict__ ow,
    const float* __restrict__ wq,  const float* __restrict__ wk,
    const float* __restrict__ wv,  const float* __restrict__ mow,
    const float* __restrict__ scaffold, const int* __restrict__ batch,
    const float* __restrict__ ipb, const float* __restrict__ bq,
    const float* __restrict__ bv,  const float* __restrict__ mob,
    const float* __restrict__ out_b)
{
    int blk = blockIdx.x;
    int tid = threadIdx.x;

    if (blk < 2048) {
        int z = blk >> 8;
        int id = (blk & 255) * 256 + tid;
        const float* src;
        __nv_bfloat16 *dh, *dl;
        size_t off;
        if (z < 3)       { src = ipw + (size_t)z * EE; dh = g_AcatH; dl = g_AcatL; off = (size_t)z * EE; }
        else if (z == 3) { src = ow;                   dh = g_AcatH; dl = g_AcatL; off = (size_t)3 * EE; }
        else {
            const float* s4[4] = {wq, wk, wv, mow};
            src = s4[z - 4]; dh = g_BcatH; dl = g_BcatL; off = (size_t)(z - 4) * EE;
        }
        float4 v = ((const float4*)src)[id];
        uint2 hi, lo;
        split4(v, hi, lo);
        *(uint2*)&dh[off + (size_t)id * 4] = hi;
        *(uint2*)&dl[off + (size_t)id * 4] = lo;
    } else if (blk < 4096) {
        int id = (blk - 2048) * 256 + tid;       // over Bb*Ee/4 = 524288
        float4 v = ((const float4*)scaffold)[id];
        uint2 hi, lo;
        split4(v, hi, lo);
        *(uint2*)&g_scafH[(size_t)id * 4] = hi;
        *(uint2*)&g_scafL[(size_t)id * 4] = lo;
    } else if (blk < 4608) {
        int n = (blk - 4096) * 256 + tid;
        if (n < Nn) {
            int b = batch[n];
            if (n == 0 || batch[n - 1] != b) g_segstart[b] = n;
        }
        if (n == 0) g_segstart[Bb] = Nn;
    } else {
        int gw = (blk - 4608) * 8 + (tid >> 5);  // 0..1535
        int lane = tid & 31;
        int which = gw / Ee, i = gw % Ee;
        const float* rowp;
        const float* vec;
        float add;
        if (which == 0)      { rowp = ipw + (size_t)i * Ee;            vec = bq;  add = ipb[i]; }
        else if (which == 1) { rowp = ipw + (size_t)(2 * Ee + i) * Ee; vec = bv;  add = ipb[2 * Ee + i]; }
        else                 { rowp = ow + (size_t)i * Ee;             vec = mob; add = out_b[i]; }
        float s = 0.f;
#pragma unroll
        for (int k = 0; k < 4; k++) {
            float4 a = ((const float4*)rowp)[lane + 32 * k];
            float4 b4 = ((const float4*)vec)[lane + 32 * k];
            s += a.x * b4.x + a.y * b4.y + a.z * b4.z + a.w * b4.w;
        }
#pragma unroll
        for (int o = 16; o; o >>= 1) s += __shfl_xor_sync(0xffffffffu, s, o);
        if (lane == 0) g_beff[gw] = s + add;
    }
}

// ================= pipelined HMMA GEMM on pre-split bf16 hi/lo =================
#define ROWB 144
#define S_AHI 0
#define S_ALO 18432
#define S_BHI 36864
#define S_BLO 46080
#define STAGE 55296
#define SM2_TOTAL (2*STAGE)

template<bool TRANSB, bool HASBIAS, bool CSPLIT>
__global__ void __launch_bounds__(256, 2)
tcgemm2(const __nv_bfloat16* __restrict__ Ahi, const __nv_bfloat16* __restrict__ Alo,
        const __nv_bfloat16* __restrict__ Bhi, const __nv_bfloat16* __restrict__ Blo,
        float* __restrict__ Cf, __nv_bfloat16* __restrict__ Chi, __nv_bfloat16* __restrict__ Clo,
        const float* __restrict__ bias,
        int K, int lda, int ldb, int ldc,
        long zA, long zB, long zC, int zBias, float alpha)
{
    extern __shared__ __align__(16) char sm[];
    uint32_t sb = smem_u32(sm);

    int z = blockIdx.z;
    Ahi += (size_t)z * zA;  Alo += (size_t)z * zA;
    Bhi += (size_t)z * zB;  Blo += (size_t)z * zB;
    int bm = blockIdx.y * 128;
    int bn = blockIdx.x * 64;
    int tid = threadIdx.x;
    int wid = tid >> 5;
    int lane = tid & 31;
    int wm = wid & 3;
    int wn = wid >> 2;

    int trow = tid >> 3, tkc = tid & 7;
    const __nv_bfloat16* pAh = Ahi + (size_t)(bm + trow) * lda + tkc * 8;
    const __nv_bfloat16* pAl = Alo + (size_t)(bm + trow) * lda + tkc * 8;
    const __nv_bfloat16* pBh;
    const __nv_bfloat16* pBl;
    if (TRANSB) {
        pBh = Bhi + (size_t)(bn + trow) * ldb + tkc * 8;
        pBl = Blo + (size_t)(bn + trow) * ldb + tkc * 8;
    } else {
        pBh = Bhi + (size_t)trow * ldb + bn + tkc * 8;
        pBl = Blo + (size_t)trow * ldb + bn + tkc * 8;
    }
    uint32_t dA = sb + (uint32_t)trow * ROWB + tkc * 16;
    uint32_t dB = sb + S_BHI + (uint32_t)trow * ROWB + tkc * 16;

#define G2_ISSUE(k0, st) do { \
    _Pragma("unroll") \
    for (int i = 0; i < 4; i++) { \
        CPA16(dA + (st) + i * 4608,         pAh + (k0) + (size_t)i * 32 * lda); \
        CPA16(dA + (st) + S_ALO + i * 4608, pAl + (k0) + (size_t)i * 32 * lda); \
    } \
    _Pragma("unroll") \
    for (int i = 0; i < 2; i++) { \
        if (TRANSB) { \
            CPA16(dB + (st) + i * 4608,                   pBh + (k0) + (size_t)i * 32 * ldb); \
            CPA16(dB + (st) + (S_BLO-S_BHI) + i * 4608,   pBl + (k0) + (size_t)i * 32 * ldb); \
        } else { \
            CPA16(dB + (st) + i * 4608,                   pBh + (size_t)((k0) + i * 32) * ldb); \
            CPA16(dB + (st) + (S_BLO-S_BHI) + i * 4608,   pBl + (size_t)((k0) + i * 32) * ldb); \
        } \
    } \
    CPA_COMMIT(); \
} while (0)

    float acc[2][4][4];
#pragma unroll
    for (int i = 0; i < 2; i++)
#pragma unroll
        for (int f = 0; f < 4; f++)
#pragma unroll
            for (int r = 0; r < 4; r++) acc[i][f][r] = 0.f;

    int am = ((lane >> 3) & 1) * 8 + (lane & 7);
    int ak = (lane >> 4) * 8;
    int bnr = ((lane >> 4) & 1) * 8 + (lane & 7);
    int bkc = ((lane >> 3) & 1) * 8;
    int bkr = ((lane >> 3) & 1) * 8 + (lane & 7);
    int bnc = (lane >> 4) * 8;

    const int nch = K / 64;
    G2_ISSUE(0, 0);

    for (int ch = 0; ch < nch; ch++) {
        bool more = (ch + 1 < nch);
        if (more) G2_ISSUE((ch + 1) * 64, ((ch + 1) & 1) * STAGE);
        if (more) CPA_WAIT1(); else CPA_WAIT0();
        __syncthreads();

        uint32_t cur = (uint32_t)(ch & 1) * STAGE;
#pragma unroll
        for (int ks = 0; ks < 4; ks++) {
            int kk = ks * 16;
            uint32_t bh[4][2], bl[4][2];
#pragma unroll
            for (int g = 0; g < 2; g++) {
                uint32_t r[4];
                if (TRANSB) {
                    uint32_t off = cur + S_BHI + (uint32_t)(wn * 32 + g * 16 + bnr) * ROWB + (kk + bkc) * 2;
                    ldsm4(r, sb + off);
                    bh[g*2][0]=r[0]; bh[g*2][1]=r[1]; bh[g*2+1][0]=r[2]; bh[g*2+1][1]=r[3];
                    ldsm4(r, sb + off + (S_BLO - S_BHI));
                    bl[g*2][0]=r[0]; bl[g*2][1]=r[1]; bl[g*2+1][0]=r[2]; bl[g*2+1][1]=r[3];
                } else {
                    uint32_t off = cur + S_BHI + (uint32_t)(kk + bkr) * ROWB + (wn * 32 + g * 16 + bnc) * 2;
                    ldsm4t(r, sb + off);
                    bh[g*2][0]=r[0]; bh[g*2][1]=r[1]; bh[g*2+1][0]=r[2]; bh[g*2+1][1]=r[3];
                    ldsm4t(r, sb + off + (S_BLO - S_BHI));
                    bl[g*2][0]=r[0]; bl[g*2][1]=r[1]; bl[g*2+1][0]=r[2]; bl[g*2+1][1]=r[3];
                }
            }
            uint32_t ah[2][4], al[2][4];
#pragma unroll
            for (int i = 0; i < 2; i++) {
                uint32_t off = cur + (uint32_t)(wm * 32 + i * 16 + am) * ROWB + (kk + ak) * 2;
                ldsm4(ah[i], sb + off);
                ldsm4(al[i], sb + off + S_ALO);
            }
#pragma unroll
            for (int i = 0; i < 2; i++)
#pragma unroll
                for (int f = 0; f < 4; f++) {
                    mma16816(acc[i][f], ah[i], bh[f]);
                    mma16816(acc[i][f], ah[i], bl[f]);
                    mma16816(acc[i][f], al[i], bh[f]);
                }
        }
        __syncthreads();
    }

#pragma unroll
    for (int i = 0; i < 2; i++) {
#pragma unroll
        for (int f = 0; f < 4; f++) {
            int row = bm + wm * 32 + i * 16 + (lane >> 2);
            int col = bn + wn * 32 + f * 8 + (lane & 3) * 2;
            float2 bb = make_float2(0.f, 0.f);
            if (HASBIAS) bb = *(const float2*)&bias[(long)z * zBias + col];
            float2 v0, v1;
            v0.x = alpha * acc[i][f][0] + bb.x;
            v0.y = alpha * acc[i][f][1] + bb.y;
            v1.x = alpha * acc[i][f][2] + bb.x;
            v1.y = alpha * acc[i][f][3] + bb.y;
            size_t o0 = (size_t)z * zC + (size_t)row * ldc + col;
            size_t o1 = (size_t)z * zC + (size_t)(row + 8) * ldc + col;
            if (CSPLIT) {
                store_split2(Chi, Clo, o0, v0);
                store_split2(Chi, Clo, o1, v1);
            } else {
                *(float2*)&Cf[o0] = v0;
                *(float2*)&Cf[o1] = v1;
            }
        }
    }
#undef G2_ISSUE
}

// ================= qhat GEMM: A-resident, cp.async double-buffered B ==========
// Writes bf16 hi/lo directly (consumed by fused_attn via cp.async).
#define Q_AHI 0
#define Q_ALO 18432
#define Q_B0  36864
#define Q_BSZ 18432
#define QH_TOTAL (Q_B0 + 2*Q_BSZ)

__global__ void __launch_bounds__(256, 2)
qhat2(const __nv_bfloat16* __restrict__ Ahi, const __nv_bfloat16* __restrict__ Alo,
      const __nv_bfloat16* __restrict__ WkH, const __nv_bfloat16* __restrict__ WkL)
{
    extern __shared__ __align__(16) char sm[];
    uint32_t sb = smem_u32(sm);

    int z = blockIdx.z;
    int bm = blockIdx.y * 128;
    const __nv_bfloat16* BH = WkH + (size_t)z * Dd * Ee;
    const __nv_bfloat16* BL = WkL + (size_t)z * Dd * Ee;

    int tid = threadIdx.x;
    int lane = tid & 31;
    int wid = tid >> 5;
    int wm = wid & 3;
    int wn = wid >> 2;

    int trow = tid >> 3, tkc = tid & 7;
    {
        const __nv_bfloat16* pAh = Ahi + (size_t)(bm + trow) * Ee + z * Dd + tkc * 8;
        const __nv_bfloat16* pAl = Alo + (size_t)(bm + trow) * Ee + z * Dd + tkc * 8;
        uint32_t dA = sb + (uint32_t)trow * ROWB + tkc * 16;
#pragma unroll
        for (int i = 0; i < 4; i++) {
            CPA16(dA + i * 4608,         pAh + (size_t)i * 32 * Ee);
            CPA16(dA + Q_ALO + i * 4608, pAl + (size_t)i * 32 * Ee);
        }
    }
    const __nv_bfloat16* pBh = BH + (size_t)trow * Ee + tkc * 8;
    const __nv_bfloat16* pBl = BL + (size_t)trow * Ee + tkc * 8;
    uint32_t dB = sb + Q_B0 + (uint32_t)trow * ROWB + tkc * 16;

#define QB_ISSUE(nt, s) do { \
    _Pragma("unroll") \
    for (int i = 0; i < 2; i++) { \
        CPA16(dB + (s) * Q_BSZ + i * 4608,        pBh + (nt) * 64 + (size_t)i * 32 * Ee); \
        CPA16(dB + (s) * Q_BSZ + 9216 + i * 4608, pBl + (nt) * 64 + (size_t)i * 32 * Ee); \
    } \
    CPA_COMMIT(); \
} while (0)

    QB_ISSUE(0, 0);
    int am = ((lane >> 3) & 1) * 8 + (lane & 7);
    int ak = (lane >> 4) * 8;
    int bkr = ((lane >> 3) & 1) * 8 + (lane & 7);
    int bnc = (lane >> 4) * 8;

    for (int nt = 0; nt < 8; nt++) {
        bool more = (nt + 1 < 8);
        if (more) QB_ISSUE(nt + 1, (nt + 1) & 1);
        if (more) CPA_WAIT1(); else CPA_WAIT0();
        __syncthreads();

        uint32_t bcur = Q_B0 + (uint32_t)(nt & 1) * Q_BSZ;
        float acc[2][4][4];
#pragma unroll
        for (int i = 0; i < 2; i++)
#pragma unroll
            for (int f = 0; f < 4; f++)
#pragma unroll
                for (int r = 0; r < 4; r++) acc[i][f][r] = 0.f;

#pragma unroll
        for (int ks = 0; ks < 4; ks++) {
            int kk = ks * 16;
            uint32_t bh[4][2], bl[4][2];
#pragma unroll
            for (int g = 0; g < 2; g++) {
                uint32_t r[4];
                uint32_t off = bcur + (uint32_t)(kk + bkr) * ROWB + (wn * 32 + g * 16 + bnc) * 2;
                ldsm4t(r, sb + off);
                bh[g*2][0]=r[0]; bh[g*2][1]=r[1]; bh[g*2+1][0]=r[2]; bh[g*2+1][1]=r[3];
                ldsm4t(r, sb + off + 9216);
                bl[g*2][0]=r[0]; bl[g*2][1]=r[1]; bl[g*2+1][0]=r[2]; bl[g*2+1][1]=r[3];
            }
            uint32_t ah[2][4], al[2][4];
#pragma unroll
            for (int i = 0; i < 2; i++) {
                uint32_t off = (uint32_t)(wm * 32 + i * 16 + am) * ROWB + (kk + ak) * 2;
                ldsm4(ah[i], sb + off);
                ldsm4(al[i], sb + off + Q_ALO);
            }
#pragma unroll
            for (int i = 0; i < 2; i++)
#pragma unroll
                for (int f = 0; f < 4; f++) {
                    mma16816(acc[i][f], ah[i], bh[f]);
                    mma16816(acc[i][f], ah[i], bl[f]);
                    mma16816(acc[i][f], al[i], bh[f]);
                }
        }

#pragma unroll
        for (int i = 0; i < 2; i++) {
#pragma unroll
            for (int f = 0; f < 4; f++) {
                int row = bm + wm * 32 + i * 16 + (lane >> 2);
                int col = nt * 64 + wn * 32 + f * 8 + (lane & 3) * 2;
                float2 v0, v1;
                v0.x = 0.125f * acc[i][f][0];
                v0.y = 0.125f * acc[i][f][1];
                v1.x = 0.125f * acc[i][f][2];
                v1.y = 0.125f * acc[i][f][3];
                size_t o0 = (size_t)row * (Hh * Ee) + (size_t)z * Ee + col;
                size_t o1 = (size_t)(row + 8) * (Hh * Ee) + (size_t)z * Ee + col;
                store_split2(g_qhatH, g_qhatL, o0, v0);
                store_split2(g_qhatH, g_qhatL, o1, v1);
            }
        }
        __syncthreads();
    }
#undef QB_ISSUE
}

// ================= fused segment attention, HMMA (qhat staged via cp.async) =====
#define XROW   1040
#define F_XHI  0
#define F_XLO  33280
#define F_QHI  66560
#define F_QLO  74880
#define F_LGP  83200
#define F_LGS  91392
#define F_PHI  92544
#define F_PLO  93056
#define F_STM  93568
#define F_STZ  93600
#define F_STF  93632
#define SMEM_FA 93664

__global__ void __launch_bounds__(256)
fused_attn_kernel(const float* __restrict__ X)
{
    extern __shared__ __align__(16) char fsm[];
    uint32_t sb = smem_u32(fsm);

    int b = blockIdx.x;
    int t = threadIdx.x;
    int w = t >> 5, lane = t & 31;
    int gid = lane >> 2, tig = lane & 3;
    int s0 = g_segstart[b], e0 = g_segstart[b + 1];

    float* stm = (float*)(fsm + F_STM);
    float* stz = (float*)(fsm + F_STZ);
    float* stf = (float*)(fsm + F_STF);
    float* lgs = (float*)(fsm + F_LGS);
    float* lgp = (float*)(fsm + F_LGP);

    // ---- stage qhat[b] bf16 hi/lo via cp.async (1024 x 16B) ----
    {
        const __nv_bfloat16* qh = g_qhatH + (size_t)b * (Hh * Ee);
        const __nv_bfloat16* ql = g_qhatL + (size_t)b * (Hh * Ee);
#pragma unroll
        for (int i = 0; i < 4; i++) {
            int idx = t + 256 * i;               // 0..1023
            int which = idx >> 9;
            int j = idx & 511;
            int h = j >> 6, piece = j & 63;
            const __nv_bfloat16* src = (which ? ql : qh) + h * Ee + piece * 8;
            uint32_t dst = sb + (which ? F_QLO : F_QHI) + (uint32_t)h * XROW + piece * 16;
            CPA16(dst, src);
        }
        CPA_COMMIT();
    }
    if (t < 8) { stm[t] = -1e30f; stz[t] = 0.f; }

    int am  = ((lane >> 3) & 1) * 8 + (lane & 7);
    int ak  = (lane >> 4) * 8;
    int bkr = ((lane >> 3) & 1) * 8 + (lane & 7);
    int bnc = (lane >> 4) * 8;
    int qrow = lane & 7;
    int qc8  = (lane >> 3) * 8;

    float acc[4][4];
#pragma unroll
    for (int mt = 0; mt < 4; mt++)
#pragma unroll
        for (int r = 0; r < 4; r++) acc[mt][r] = 0.f;

    for (int base = s0; base < e0; base += 32) {
        int cnt = min(32, e0 - base);

#pragma unroll
        for (int i = 0; i < 16; i++) {
            int flat = t + 256 * i;
            int node = flat >> 7, c4 = flat & 127;
            float4 v = make_float4(0.f, 0.f, 0.f, 0.f);
            if (node < cnt)
                v = *(const float4*)&X[(size_t)(base + node) * Ee + c4 * 4];
            uint2 hi, lo;
            split4(v, hi, lo);
            uint32_t off = (uint32_t)node * XROW + (uint32_t)c4 * 8;
            *(uint2*)(fsm + F_XHI + off) = hi;
            *(uint2*)(fsm + F_XLO + off) = lo;
        }
        CPA_WAIT0();            // first iter: qhat copies done; later: no-op
        __syncthreads();

        {
            float lg[2][4];
#pragma unroll
            for (int m = 0; m < 2; m++)
#pragma unroll
                for (int r = 0; r < 4; r++) lg[m][r] = 0.f;

            int ks0 = w * 64;
#pragma unroll
            for (int kb = 0; kb < 2; kb++) {
                int kbase = ks0 + kb * 32;
                uint32_t rq[4];
                uint32_t qoff = (uint32_t)qrow * XROW + (uint32_t)(kbase + qc8) * 2;
                uint32_t bqh[2][2], bql[2][2];
                ldsm4(rq, sb + F_QHI + qoff);
                bqh[0][0]=rq[0]; bqh[0][1]=rq[1]; bqh[1][0]=rq[2]; bqh[1][1]=rq[3];
                ldsm4(rq, sb + F_QLO + qoff);
                bql[0][0]=rq[0]; bql[0][1]=rq[1]; bql[1][0]=rq[2]; bql[1][1]=rq[3];
#pragma unroll
                for (int ks = 0; ks < 2; ks++) {
                    int kk = kbase + ks * 16;
                    uint32_t ah[2][4], al[2][4];
#pragma unroll
                    for (int m = 0; m < 2; m++) {
                        uint32_t aoff = (uint32_t)(m * 16 + am) * XROW + (uint32_t)(kk + ak) * 2;
                        ldsm4(ah[m], sb + F_XHI + aoff);
                        ldsm4(al[m], sb + F_XLO + aoff);
                    }
#pragma unroll
                    for (int m = 0; m < 2; m++) {
                        mma16816(lg[m], ah[m], bqh[ks]);
                        mma16816(lg[m], ah[m], bql[ks]);
                        mma16816(lg[m], al[m], bqh[ks]);
                    }
                }
            }
            float* lp = lgp + w * 256;
#pragma unroll
            for (int m = 0; m < 2; m++) {
                lp[(m * 16 + gid) * 8 + 2 * tig]     = lg[m][0];
                lp[(m * 16 + gid) * 8 + 2 * tig + 1] = lg[m][1];
                lp[(m * 16 + gid + 8) * 8 + 2 * tig]     = lg[m][2];
                lp[(m * 16 + gid + 8) * 8 + 2 * tig + 1] = lg[m][3];
            }
        }
        __syncthreads();

        {
            float s = 0.f;
#pragma unroll
            for (int w2 = 0; w2 < 8; w2++) s += lgp[w2 * 256 + t];
            lgs[(t >> 3) * 9 + (t & 7)] = s;
        }
        __syncthreads();

        {
            float v = (lane < cnt) ? lgs[lane * 9 + w] : -1e30f;
            float mx = v;
#pragma unroll
            for (int o = 16; o; o >>= 1) mx = fmaxf(mx, __shfl_xor_sync(0xffffffffu, mx, o));
            float mo = stm[w];
            float mn = fmaxf(mo, mx);
            float p = (lane < cnt) ? __expf(v - mn) : 0.f;
            __nv_bfloat16 ph = __float2bfloat16(p);
            __nv_bfloat16 pl = __float2bfloat16(p - __bfloat162float(ph));
            ((__nv_bfloat16*)(fsm + F_PHI))[lane * 8 + w] = ph;
            ((__nv_bfloat16*)(fsm + F_PLO))[lane * 8 + w] = pl;
            float ssum = p;
#pragma unroll
            for (int o = 16; o; o >>= 1) ssum += __shfl_xor_sync(0xffffffffu, ssum, o);
            if (lane == 0) {
                float f = __expf(mo - mn);
                stf[w] = f;
                stm[w] = mn;
                stz[w] = stz[w] * f + ssum;
            }
        }
        __syncthreads();

        {
            float f0 = stf[2 * tig];
            float f1 = stf[2 * tig + 1];
#pragma unroll
            for (int mt = 0; mt < 4; mt++) {
                acc[mt][0] *= f0; acc[mt][1] *= f1;
                acc[mt][2] *= f0; acc[mt][3] *= f1;
            }
            uint32_t rp[4];
            uint32_t bph[2][2], bpl[2][2];
            ldsm4t(rp, sb + F_PHI + (uint32_t)lane * 16);
            bph[0][0]=rp[0]; bph[0][1]=rp[1]; bph[1][0]=rp[2]; bph[1][1]=rp[3];
            ldsm4t(rp, sb + F_PLO + (uint32_t)lane * 16);
            bpl[0][0]=rp[0]; bpl[0][1]=rp[1]; bpl[1][0]=rp[2]; bpl[1][1]=rp[3];

#pragma unroll
            for (int ks = 0; ks < 2; ks++) {
#pragma unroll
                for (int mt = 0; mt < 4; mt++) {
                    uint32_t aoff = (uint32_t)(ks * 16 + bkr) * XROW
                                  + (uint32_t)(w * 64 + mt * 16 + bnc) * 2;
                    uint32_t ra[4], rl[4];
                    ldsm4t(ra, sb + F_XHI + aoff);
                    ldsm4t(rl, sb + F_XLO + aoff);
                    uint32_t ah2[4] = {ra[0], ra[2], ra[1], ra[3]};
                    uint32_t al2[4] = {rl[0], rl[2], rl[1], rl[3]};
                    mma16816(acc[mt], ah2, bph[ks]);
                    mma16816(acc[mt], al2, bph[ks]);
                    mma16816(acc[mt], ah2, bpl[ks]);
                }
            }
        }
        __syncthreads();
    }

    float rz0 = 1.f / stz[2 * tig];
    float rz1 = 1.f / stz[2 * tig + 1];
    float* fxw = (float*)(fsm + F_XHI);
#pragma unroll
    for (int mt = 0; mt < 4; mt++) {
        int col = w * 64 + mt * 16;
        fxw[(2 * tig) * 520 + col + gid]         = acc[mt][0] * rz0;
        fxw[(2 * tig + 1) * 520 + col + gid]     = acc[mt][1] * rz1;
        fxw[(2 * tig) * 520 + col + 8 + gid]     = acc[mt][2] * rz0;
        fxw[(2 * tig + 1) * 520 + col + 8 + gid] = acc[mt][3] * rz1;
    }
    __syncthreads();
#pragma unroll
    for (int i = 0; i < 8; i++) {
        int idx = t + 256 * i;
        int h = idx >> 8, cp = (idx & 255) * 2;
        float2 v = make_float2(fxw[h * 520 + cp], fxw[h * 520 + cp + 1]);
        store_split2(g_xwH, g_xwL, ((size_t)b * Hh + h) * Ee + cp, v);
    }
}

// ---------------- LayerNorm ----------------
__global__ void __launch_bounds__(256) ln_kernel(const float* __restrict__ lng,
                                                 const float* __restrict__ lnb,
                                                 float* __restrict__ out)
{
    int b = blockIdx.x;
    int t = threadIdx.x;
    float v0 = g_outbuf[(long)b * Ee + t];
    float v1 = g_outbuf[(long)b * Ee + t + 256];
    float s = v0 + v1;
    float q = v0 * v0 + v1 * v1;
#pragma unroll
    for (int o = 16; o; o >>= 1) {
        s += __shfl_xor_sync(0xffffffffu, s, o);
        q += __shfl_xor_sync(0xffffffffu, q, o);
    }
    __shared__ float ss[8], qs[8];
    __shared__ float mu_s, r_s;
    int wid = t >> 5, lane = t & 31;
    if (lane == 0) { ss[wid] = s; qs[wid] = q; }
    __syncthreads();
    if (t == 0) {
        float S = 0.f, Q = 0.f;
#pragma unroll
        for (int i = 0; i < 8; i++) { S += ss[i]; Q += qs[i]; }
        float mu = S / (float)Ee;
        float var = Q / (float)Ee - mu * mu;
        mu_s = mu;
        r_s = 1.f / sqrtf(var + 1e-5f);
    }
    __syncthreads();
    float mu = mu_s, r = r_s;
    out[(long)b * Ee + t]       = (v0 - mu) * r * lng[t]       + lnb[t];
    out[(long)b * Ee + t + 256] = (v1 - mu) * r * lng[t + 256] + lnb[t + 256];
}

// ---------------- launch ----------------
extern "C" void kernel_launch(void* const* d_in, const int* in_sizes, int n_in,
                              void* d_out, int out_size)
{
    (void)in_sizes; (void)n_in; (void)out_size;
    const float* X        = (const float*)d_in[0];
    const float* scaffold = (const float*)d_in[1];
    const float* Wq       = (const float*)d_in[2];
    const float* bq       = (const float*)d_in[3];
    const float* Wk       = (const float*)d_in[4];
    const float* Wv       = (const float*)d_in[6];
    const float* bv       = (const float*)d_in[7];
    const float* ipw      = (const float*)d_in[8];
    const float* ipb      = (const float*)d_in[9];
    const float* mow      = (const float*)d_in[10];
    const float* mob      = (const float*)d_in[11];
    const float* ow       = (const float*)d_in[12];
    const float* ob       = (const float*)d_in[13];
    const float* lng      = (const float*)d_in[14];
    const float* lnb      = (const float*)d_in[15];
    const int*   batch    = (const int*)d_in[16];

    void* p;
    cudaGetSymbolAddress(&p, g_AcatH);   __nv_bfloat16* AcatH = (__nv_bfloat16*)p;
    cudaGetSymbolAddress(&p, g_AcatL);   __nv_bfloat16* AcatL = (__nv_bfloat16*)p;
    cudaGetSymbolAddress(&p, g_BcatH);   __nv_bfloat16* BcatH = (__nv_bfloat16*)p;
    cudaGetSymbolAddress(&p, g_BcatL);   __nv_bfloat16* BcatL = (__nv_bfloat16*)p;
    cudaGetSymbolAddress(&p, g_scafH);   __nv_bfloat16* scafH = (__nv_bfloat16*)p;
    cudaGetSymbolAddress(&p, g_scafL);   __nv_bfloat16* scafL = (__nv_bfloat16*)p;
    cudaGetSymbolAddress(&p, g_WeffH);   __nv_bfloat16* WeffH = (__nv_bfloat16*)p;
    cudaGetSymbolAddress(&p, g_WeffL);   __nv_bfloat16* WeffL = (__nv_bfloat16*)p;
    cudaGetSymbolAddress(&p, g_qqH);     __nv_bfloat16* qqH   = (__nv_bfloat16*)p;
    cudaGetSymbolAddress(&p, g_qqL);     __nv_bfloat16* qqL   = (__nv_bfloat16*)p;
    cudaGetSymbolAddress(&p, g_xwH);     __nv_bfloat16* xwH   = (__nv_bfloat16*)p;
    cudaGetSymbolAddress(&p, g_xwL);     __nv_bfloat16* xwL   = (__nv_bfloat16*)p;
    cudaGetSymbolAddress(&p, g_pooledH); __nv_bfloat16* plH   = (__nv_bfloat16*)p;
    cudaGetSymbolAddress(&p, g_pooledL); __nv_bfloat16* plL   = (__nv_bfloat16*)p;
    cudaGetSymbolAddress(&p, g_beff);    float* beff  = (float*)p;
    cudaGetSymbolAddress(&p, g_outbuf);  float* outbuf = (float*)p;

    cudaFuncSetAttribute(tcgemm2<false, false, true>,
                         cudaFuncAttributeMaxDynamicSharedMemorySize, SM2_TOTAL);
    cudaFuncSetAttribute(tcgemm2<true, true, true>,
                         cudaFuncAttributeMaxDynamicSharedMemorySize, SM2_TOTAL);
    cudaFuncSetAttribute(tcgemm2<true, true, false>,
                         cudaFuncAttributeMaxDynamicSharedMemorySize, SM2_TOTAL);
    cudaFuncSetAttribute(qhat2,
                         cudaFuncAttributeMaxDynamicSharedMemorySize, QH_TOTAL);
    cudaFuncSetAttribute(fused_attn_kernel,
                         cudaFuncAttributeMaxDynamicSharedMemorySize, SMEM_FA);

    // ALL independent preprocessing in one launch
    prep<<<4800, 256>>>(ipw, ow, Wq, Wk, Wv, mow, scaffold, batch,
                        ipb, bq, bv, mob, ob);

    // fold: Weff[z] = Acat[z] @ Bcat[z] (NN), write hi/lo
    tcgemm2<false, false, true><<<dim3(8, 4, 4), 256, SM2_TOTAL>>>(
        AcatH, AcatL, BcatH, BcatL, nullptr, WeffH, WeffL, nullptr,
        512, 512, 512, 512, (long)EE, (long)EE, (long)EE, 0, 1.f);

    // qq = scaffold @ Wq_eff^T + bq_eff (NT), write hi/lo
    tcgemm2<true, true, true><<<dim3(8, 32, 1), 256, SM2_TOTAL>>>(
        scafH, scafL, WeffH, WeffL, nullptr, qqH, qqL, beff,
        512, Ee, Ee, Ee, 0, 0, 0, 0, 1.f);

    // qhat (A-resident, pipelined; writes bf16 hi/lo)
    qhat2<<<dim3(1, 32, 8), 256, QH_TOTAL>>>(qqH, qqL, WeffH + EE, WeffL + EE);

    fused_attn_kernel<<<Bb, 256, SMEM_FA>>>(X);

    // pooled = xw @ Wv_eff_h^T + bv_eff (NT), write hi/lo
    tcgemm2<true, true, true><<<dim3(1, 32, 8), 256, SM2_TOTAL>>>(
        xwH, xwL, WeffH + 2 * EE, WeffL + 2 * EE, nullptr, plH, plL, beff + Ee,
        512, Hh * Ee, Ee, Ee, (long)Ee, (long)Dd * Ee, (long)Dd, Dd, 1.f);

    // out = pooled @ Wo_eff^T + bo_eff (NT), write fp32
    tcgemm2<true, true, false><<<dim3(8, 32, 1), 256, SM2_TOTAL>>>(
        plH, plL, WeffH + 3 * EE, WeffL + 3 * EE, outbuf, nullptr, nullptr, beff + 2 * Ee,
        512, Ee, Ee, Ee, 0, 0, 0, 0, 1.f);

    ln_kernel<<<Bb, 256>>>(lng, lnb, (float*)d_out);
}